// round 13
// baseline (speedup 1.0000x reference)
#include <cuda_runtime.h>
#include <cuda_fp16.h>
#include <math.h>
#include <stdint.h>

#define Bb   16
#define Ss   1024
#define Ee   256
#define Hh   256
#define FHh  512
#define Vv   8000
#define WSw  5
#define NTOK (Bb*Ss)     /* 16384 */
#define G4H  (4*Hh)      /* 1024  */

// ---------------- scratch (device globals; no dynamic allocation) ----------
__device__ float g_PVp[2][(size_t)Vv * G4H];            // permuted-col input projections
__device__ __half g_hA[2][2][(size_t)NTOK * Hh];        // [dir][pingpong] h as fp16
__device__ float g_cst[2][(size_t)NTOK * Hh];           // [dir] c state
__device__ __half g_fcA[(size_t)NTOK * FHh];            // leaky(h) concat, fc1 A (fp16)
__device__ float g_fc1[(size_t)NTOK * FHh];
// fp16 weights, col-permuted, pre-swizzled tiles (128 rows x 64 k = 16KB)
__device__ unsigned char g_Bsw[2][8][4][16384];         // Whh  [dir][nblk][kc]
__device__ unsigned char g_BswIH[2][8][4][16384];       // Wih  [dir][nblk][kc]
__device__ unsigned char g_fc1Bsw[4][8][16384];         // fc1_w [nblk][kc]
__device__ float g_bsum[2][G4H];                        // permuted bih+bhh

__device__ __forceinline__ float sigmoidf_(float x) { return 1.0f / (1.0f + expf(-x)); }
__device__ __forceinline__ float leakyf_(float x)   { return x > 0.0f ? x : 0.01f * x; }
__device__ __forceinline__ uint32_t swz128(uint32_t off) { return off ^ ((off >> 3) & 0x70); }
__device__ __forceinline__ uint32_t smem_u32(const void* p) {
    uint32_t a;
    asm("{ .reg .u64 t; cvta.to.shared.u64 t, %1; cvt.u32.u64 %0, t; }" : "=r"(a) : "l"(p));
    return a;
}
__device__ __forceinline__ void ldsm4(uint32_t* r, uint32_t addr) {
    asm volatile("ldmatrix.sync.aligned.m8n8.x4.shared.b16 {%0,%1,%2,%3}, [%4];"
        : "=r"(r[0]), "=r"(r[1]), "=r"(r[2]), "=r"(r[3]) : "r"(addr));
}
__device__ __forceinline__ void mma_f16(float* d, const uint32_t* a, const uint32_t* b) {
    asm volatile("mma.sync.aligned.m16n8k16.row.col.f32.f16.f16.f32 "
        "{%0,%1,%2,%3}, {%4,%5,%6,%7}, {%8,%9}, {%0,%1,%2,%3};"
        : "+f"(d[0]), "+f"(d[1]), "+f"(d[2]), "+f"(d[3])
        : "r"(a[0]), "r"(a[1]), "r"(a[2]), "r"(a[3]), "r"(b[0]), "r"(b[1]));
}
__device__ __forceinline__ void cpasync16(uint32_t dst, const void* src) {
    asm volatile("cp.async.cg.shared.global [%0], [%1], 16;" :: "r"(dst), "l"(src));
}
#define CPASYNC_COMMIT() asm volatile("cp.async.commit_group;" ::: "memory")
#define CPASYNC_WAIT_1() asm volatile("cp.async.wait_group 1;" ::: "memory")
#define CPASYNC_WAIT_0() asm volatile("cp.async.wait_group 0;" ::: "memory")

__device__ __forceinline__ uint32_t packh(__half a, __half b) {
    unsigned short ua = *(unsigned short*)&a, ub = *(unsigned short*)&b;
    return (uint32_t)ua | ((uint32_t)ub << 16);
}

#define PV_SMEM  (1024 + 32768 + 512)
#define SB_SMEM  (1024 + 65536 + 512)   /* 2 x 32KB stages (Acc 64KB reuse); bias */

// ---------------------------------------------------------------------------
// prep_all: blocks [0,256) Whh (+bias), [256,512) Wih, [512,640) fc1_w.
// fp16 RN, permutation p = unit*4+gate for Whh/Wih, pre-swizzled.
// ---------------------------------------------------------------------------
__global__ void __launch_bounds__(256) prep_all(const float* __restrict__ Whf, const float* __restrict__ Whb,
                                                const float* __restrict__ Wif, const float* __restrict__ Wib,
                                                const float* __restrict__ fc1w,
                                                const float* __restrict__ bihf, const float* __restrict__ bhhf,
                                                const float* __restrict__ bihb, const float* __restrict__ bhhb)
{
    const int blk = blockIdx.x;
    const int tid = threadIdx.x;
    if (blk < 512) {
        const int sect = blk >> 8;                       // 0 = Whh, 1 = Wih
        int idx = (blk & 255) * 256 + tid;               // 65536 per section
        int dir = idx >> 15;
        int r = idx & 32767;
        int n = r >> 5;
        int k8 = (r & 31) << 3;
        const float* W = sect ? (dir ? Wib : Wif) : (dir ? Whb : Whf);
        int p = ((n & 255) << 2) | (n >> 8);             // unit*4 + gate
        int nblk = p >> 7, prow = p & 127;
        float4 v0 = *(const float4*)(W + (size_t)n * Hh + k8);
        float4 v1 = *(const float4*)(W + (size_t)n * Hh + k8 + 4);
        float vals[8] = {v0.x, v0.y, v0.z, v0.w, v1.x, v1.y, v1.z, v1.w};
#pragma unroll
        for (int j = 0; j < 8; j++) {
            int k = k8 + j;
            int kc = k >> 6, kb = k & 63;
            uint32_t off = swz128((uint32_t)prow * 128u + (uint32_t)kb * 2u);
            __half hv = __float2half(vals[j]);
            if (sect == 0) *(__half*)(&g_Bsw[dir][nblk][kc][off]) = hv;
            else           *(__half*)(&g_BswIH[dir][nblk][kc][off]) = hv;
        }
        if (sect == 0 && k8 == 0) {
            const float* bi = dir ? bihb : bihf;
            const float* bh = dir ? bhhb : bhhf;
            g_bsum[dir][p] = bi[n] + bh[n];
        }
    } else {
        int idx = (blk - 512) * 256 + tid;               // 32768 threads
        int n = idx >> 6;                                // 0..511
        int k8 = (idx & 63) << 3;
        int nblk = n >> 7, prow = n & 127;
        float4 v0 = *(const float4*)(fc1w + (size_t)n * FHh + k8);
        float4 v1 = *(const float4*)(fc1w + (size_t)n * FHh + k8 + 4);
        float vals[8] = {v0.x, v0.y, v0.z, v0.w, v1.x, v1.y, v1.z, v1.w};
#pragma unroll
        for (int j = 0; j < 8; j++) {
            int k = k8 + j;
            int kc = k >> 6, kb = k & 63;
            uint32_t off = swz128((uint32_t)prow * 128u + (uint32_t)kb * 2u);
            *(__half*)(&g_fc1Bsw[nblk][kc][off]) = __float2half(vals[j]);
        }
    }
}

// ---------------------------------------------------------------------------
// pv_mma: PVp[dir] = embed(row0=0) @ Wih^T, permuted cols, fp16 1-term.
// smem: A 16KB | B 16KB. grid (8 nblk, 63 mtile, 2 dir).
// ---------------------------------------------------------------------------
__global__ void __launch_bounds__(256) pv_mma(const float* __restrict__ embed)
{
    extern __shared__ unsigned char smraw[];
    uint32_t sb0 = smem_u32(smraw);
    uint32_t sb = (sb0 + 1023u) & ~1023u;
    unsigned char* smb = smraw + (sb - sb0);

    const int dir = blockIdx.z;
    const int nblk = blockIdx.x;
    const int m0 = blockIdx.y << 7;
    const int tid = threadIdx.x;
    const int lane = tid & 31, wid = tid >> 5;
    const int wm = wid >> 2, wn = wid & 3;

    float acc[4][4][4];
#pragma unroll
    for (int a = 0; a < 4; a++)
#pragma unroll
        for (int b = 0; b < 4; b++)
#pragma unroll
            for (int c = 0; c < 4; c++) acc[a][b][c] = 0.f;

    const uint32_t aBase = sb, bBase = sb + 16384u;
    const int arow = (wm << 6) + (lane & 15);
    const int atop = (lane >> 4) << 4;
    const int brow = (wn << 5) + (lane & 7) + ((lane & 16) ? 8 : 0);
    const int btop = (lane & 8) ? 16 : 0;

    for (int kc = 0; kc < 4; kc++) {
#pragma unroll
        for (int i = 0; i < 4; i++) {
            int u = tid + (i << 8);
            int r = u >> 3, c8 = u & 7;
            int g = m0 + r;
            float vals[8];
            if (g == 0 || g >= Vv) {
#pragma unroll
                for (int j = 0; j < 8; j++) vals[j] = 0.f;
            } else {
                float4 v0 = *(const float4*)(embed + (size_t)g * Ee + (kc << 6) + (c8 << 3));
                float4 v1 = *(const float4*)(embed + (size_t)g * Ee + (kc << 6) + (c8 << 3) + 4);
                vals[0] = v0.x; vals[1] = v0.y; vals[2] = v0.z; vals[3] = v0.w;
                vals[4] = v1.x; vals[5] = v1.y; vals[6] = v1.z; vals[7] = v1.w;
            }
            uint4 hv;
            hv.x = packh(__float2half(vals[0]), __float2half(vals[1]));
            hv.y = packh(__float2half(vals[2]), __float2half(vals[3]));
            hv.z = packh(__float2half(vals[4]), __float2half(vals[5]));
            hv.w = packh(__float2half(vals[6]), __float2half(vals[7]));
            *(uint4*)(smb + swz128((uint32_t)r * 128u + ((uint32_t)c8 << 4))) = hv;
        }
        {
            const uint4* src = (const uint4*)&g_BswIH[dir][nblk][kc][0];
            uint4* dst = (uint4*)(smb + 16384);
#pragma unroll
            for (int i = 0; i < 4; i++) dst[tid + (i << 8)] = src[tid + (i << 8)];
        }
        __syncthreads();

#pragma unroll
        for (int ks = 0; ks < 4; ks++) {
            const uint32_t kbyte = (uint32_t)ks << 5;
            uint32_t ah[4][4], bh[8];
#pragma unroll
            for (int mi = 0; mi < 4; mi++) {
                uint32_t off = swz128((uint32_t)(arow + mi * 16) * 128u + kbyte + (uint32_t)atop);
                ldsm4(ah[mi], aBase + off);
            }
#pragma unroll
            for (int bi = 0; bi < 2; bi++) {
                uint32_t off = swz128((uint32_t)(brow + bi * 16) * 128u + kbyte + (uint32_t)btop);
                ldsm4(bh + bi * 4, bBase + off);
            }
#pragma unroll
            for (int mi = 0; mi < 4; mi++)
#pragma unroll
                for (int ni = 0; ni < 4; ni++)
                    mma_f16(acc[mi][ni], ah[mi], bh + ni * 2);
        }
        __syncthreads();
    }

    float* out = g_PVp[dir];
#pragma unroll
    for (int mi = 0; mi < 4; mi++) {
        int r0 = m0 + (wm << 6) + mi * 16 + (lane >> 2);
#pragma unroll
        for (int ni = 0; ni < 4; ni++) {
            int c0 = (nblk << 7) + (wn << 5) + ni * 8 + ((lane & 3) << 1);
            if (r0 < Vv)
                *(float2*)(out + (size_t)r0 * G4H + c0) = make_float2(acc[mi][ni][0], acc[mi][ni][1]);
            if (r0 + 8 < Vv)
                *(float2*)(out + (size_t)(r0 + 8) * G4H + c0) = make_float2(acc[mi][ni][2], acc[mi][ni][3]);
        }
    }
}

// ---------------------------------------------------------------------------
// gates_init: step 0 exactly (h0 = c0 = 0)
// ---------------------------------------------------------------------------
__global__ void __launch_bounds__(256) gates_init(const int* __restrict__ x)
{
    int idx = blockIdx.x * 256 + threadIdx.x;          // 2 * 16384 * 32
    int dir = idx >> 19;
    int r = idx & 524287;
    int row = r >> 5;
    int u8 = (r & 31) << 3;
    int t = row & (Ss - 1), bidx = row >> 10;
    int tp = dir ? (t + WSw) : (t - WSw);
    bool valid = ((unsigned)tp < (unsigned)Ss);
    int tok = valid ? x[(bidx << 10) + tp] : 0;
    const float* pv = g_PVp[dir] + (size_t)tok * G4H + (u8 << 2);
    const float* bs = g_bsum[dir] + (u8 << 2);
    float* crow = g_cst[dir] + (size_t)row * Hh + u8;
    __half* hrow = g_hA[dir][1] + (size_t)row * Hh + u8;

    float c8[8];
    uint32_t hw[4];
#pragma unroll
    for (int j = 0; j < 8; j += 2) {
        float g0[4], g1[4];
#pragma unroll
        for (int q = 0; q < 4; q++) {
            g0[q] = bs[j * 4 + q];
            g1[q] = bs[j * 4 + 4 + q];
        }
        if (valid) {
            float4 p0 = *(const float4*)(pv + j * 4);
            float4 p1 = *(const float4*)(pv + j * 4 + 4);
            g0[0] += p0.x; g0[1] += p0.y; g0[2] += p0.z; g0[3] += p0.w;
            g1[0] += p1.x; g1[1] += p1.y; g1[2] += p1.z; g1[3] += p1.w;
        }
        float cn0 = sigmoidf_(g0[0]) * tanhf(g0[2]);
        float cn1 = sigmoidf_(g1[0]) * tanhf(g1[2]);
        float h0 = sigmoidf_(g0[3]) * tanhf(cn0);
        float h1 = sigmoidf_(g1[3]) * tanhf(cn1);
        c8[j] = cn0; c8[j + 1] = cn1;
        hw[j >> 1] = packh(__float2half(h0), __float2half(h1));
    }
    *(float4*)crow       = make_float4(c8[0], c8[1], c8[2], c8[3]);
    *(float4*)(crow + 4) = make_float4(c8[4], c8[5], c8[6], c8[7]);
    *(uint4*)hrow = make_uint4(hw[0], hw[1], hw[2], hw[3]);
}

// ---------------------------------------------------------------------------
// gates_mma: steps 1..5, both dirs. fp16 1-term, 2-stage cp.async pipeline
// (2 x 32KB stages), 2 CTAs/SM; fused LSTM epilogue.
// ---------------------------------------------------------------------------
__global__ void __launch_bounds__(256, 2) gates_mma(const int* __restrict__ x, int step)
{
    extern __shared__ unsigned char smraw[];
    uint32_t sb0 = smem_u32(smraw);
    uint32_t sb = (sb0 + 1023u) & ~1023u;
    unsigned char* smb = smraw + (sb - sb0);

    const int dir = blockIdx.z;
    const int nblk = blockIdx.x;
    const int m0 = blockIdx.y << 7;
    const int tid = threadIdx.x;
    const int lane = tid & 31, wid = tid >> 5;
    const int wm = wid >> 2, wn = wid & 3;
    const int buf = step & 1, nbuf = buf ^ 1;

    float* biasf = (float*)(smb + 65536);
    if (tid < 32)
        *(float4*)(biasf + (tid << 2)) = *(const float4*)(g_bsum[dir] + (nblk << 7) + (tid << 2));

    const uint4* srcA = (const uint4*)g_hA[dir][buf];

    auto issue = [&](int kcx, int stg) {
        const uint32_t sbase = sb + (uint32_t)stg * 32768u;
#pragma unroll
        for (int i = 0; i < 4; i++) {
            int u = tid + (i << 8);
            int r = u >> 3, c16 = u & 7;
            uint32_t dst = sbase + swz128((uint32_t)r * 128u + ((uint32_t)c16 << 4));
            cpasync16(dst, &srcA[(size_t)(m0 + r) * 32 + (kcx << 3) + c16]);
        }
        const unsigned char* src = &g_Bsw[dir][nblk][kcx][0];
#pragma unroll
        for (int i = 0; i < 4; i++) {
            uint32_t o = ((uint32_t)tid + ((uint32_t)i << 8)) << 4;
            cpasync16(sbase + 16384u + o, src + o);
        }
        CPASYNC_COMMIT();
    };

    float acc[4][4][4];
#pragma unroll
    for (int a = 0; a < 4; a++)
#pragma unroll
        for (int b = 0; b < 4; b++)
#pragma unroll
            for (int c = 0; c < 4; c++) acc[a][b][c] = 0.f;

    const int arow = (wm << 6) + (lane & 15);
    const int atop = (lane >> 4) << 4;
    const int brow = (wn << 5) + (lane & 7) + ((lane & 16) ? 8 : 0);
    const int btop = (lane & 8) ? 16 : 0;

    issue(0, 0);
    for (int kc = 0; kc < 4; kc++) {
        const int stg = kc & 1;
        if (kc < 3) { issue(kc + 1, stg ^ 1); CPASYNC_WAIT_1(); }
        else        { CPASYNC_WAIT_0(); }
        __syncthreads();

        const uint32_t aB = sb + (uint32_t)stg * 32768u, bB = aB + 16384u;
#pragma unroll
        for (int ks = 0; ks < 4; ks++) {
            const uint32_t kbyte = (uint32_t)ks << 5;
            uint32_t ah[4][4], bh[8];
#pragma unroll
            for (int mi = 0; mi < 4; mi++) {
                uint32_t off = swz128((uint32_t)(arow + mi * 16) * 128u + kbyte + (uint32_t)atop);
                ldsm4(ah[mi], aB + off);
            }
#pragma unroll
            for (int bi = 0; bi < 2; bi++) {
                uint32_t off = swz128((uint32_t)(brow + bi * 16) * 128u + kbyte + (uint32_t)btop);
                ldsm4(bh + bi * 4, bB + off);
            }
#pragma unroll
            for (int mi = 0; mi < 4; mi++)
#pragma unroll
                for (int ni = 0; ni < 4; ni++)
                    mma_f16(acc[mi][ni], ah[mi], bh + ni * 2);
        }
        __syncthreads();
    }

    // stage accumulators into smem (unions over both stages; safe post-sync)
    float* Acc = (float*)smb;
#pragma unroll
    for (int mi = 0; mi < 4; mi++)
#pragma unroll
        for (int ni = 0; ni < 4; ni++) {
            int r0 = (wm << 6) + mi * 16 + (lane >> 2);
            int c0 = (wn << 5) + ni * 8 + ((lane & 3) << 1);
            *(float2*)(Acc + r0 * 128 + c0) = make_float2(acc[mi][ni][0], acc[mi][ni][1]);
            *(float2*)(Acc + (r0 + 8) * 128 + c0) = make_float2(acc[mi][ni][2], acc[mi][ni][3]);
        }
    __syncthreads();

    // fused epilogue: 2 threads per row, 16 units each
    const int row_l = tid >> 1;
    const int half = tid & 1;
    const int row = m0 + row_l;
    const int t = row & (Ss - 1), bidx = row >> 10;
    const int tp = dir ? (t + WSw - step) : (t - WSw + step);
    const bool valid = ((unsigned)tp < (unsigned)Ss);
    const int tok = valid ? x[(bidx << 10) + tp] : 0;
    const bool finalstep = (step == WSw);

    const float4* accu = (const float4*)(Acc + row_l * 128 + (half << 6));
    const float4* bsu  = (const float4*)(biasf + (half << 6));
    const float4* pvu  = (const float4*)(g_PVp[dir] + (size_t)tok * G4H + (nblk << 7) + (half << 6));
    float4* cp = (float4*)(g_cst[dir] + (size_t)row * Hh + (nblk << 5) + (half << 4));
    const int colbase = (nblk << 5) + (half << 4);
    __half* hip = g_hA[dir][nbuf] + (size_t)row * Hh + colbase;
    __half* fHp = g_fcA + (size_t)row * FHh + dir * Hh + colbase;

    uint32_t hwH[8], fwH[8];
#pragma unroll
    for (int g4 = 0; g4 < 4; g4++) {
        float4 cv = cp[g4];
        float cin[4] = {cv.x, cv.y, cv.z, cv.w};
        float ho[4];
#pragma unroll
        for (int j = 0; j < 4; j++) {
            int u = g4 * 4 + j;
            float4 gq = accu[u];
            float4 bq = bsu[u];
            float pi = gq.x + bq.x, pf = gq.y + bq.y, pg = gq.z + bq.z, po = gq.w + bq.w;
            if (valid) {
                float4 pq = pvu[u];
                pi += pq.x; pf += pq.y; pg += pq.z; po += pq.w;
            }
            float iv = sigmoidf_(pi), fv = sigmoidf_(pf), gv = tanhf(pg), ov = sigmoidf_(po);
            float cn = fv * cin[j] + iv * gv;
            cin[j] = cn;
            ho[j] = ov * tanhf(cn);
        }
        cp[g4] = make_float4(cin[0], cin[1], cin[2], cin[3]);
        hwH[g4 * 2 + 0] = packh(__float2half(ho[0]), __float2half(ho[1]));
        hwH[g4 * 2 + 1] = packh(__float2half(ho[2]), __float2half(ho[3]));
        if (finalstep) {
            fwH[g4 * 2 + 0] = packh(__float2half(leakyf_(ho[0])), __float2half(leakyf_(ho[1])));
            fwH[g4 * 2 + 1] = packh(__float2half(leakyf_(ho[2])), __float2half(leakyf_(ho[3])));
        }
    }
    *(uint4*)hip       = make_uint4(hwH[0], hwH[1], hwH[2], hwH[3]);
    *(uint4*)(hip + 8) = make_uint4(hwH[4], hwH[5], hwH[6], hwH[7]);
    if (finalstep) {
        *(uint4*)fHp       = make_uint4(fwH[0], fwH[1], fwH[2], fwH[3]);
        *(uint4*)(fHp + 8) = make_uint4(fwH[4], fwH[5], fwH[6], fwH[7]);
    }
}

// ---------------------------------------------------------------------------
// fc1_mma: g_fc1 = leaky( fcA @ fc1_w^T + fc1_b ). fp16 1-term, 2-stage
// pipeline, 2 CTAs/SM. grid (4 nblk, 128 mtile). K=512 in 8 chunks.
// ---------------------------------------------------------------------------
__global__ void __launch_bounds__(256, 2) fc1_mma(const float* __restrict__ fc1_b)
{
    extern __shared__ unsigned char smraw[];
    uint32_t sb0 = smem_u32(smraw);
    uint32_t sb = (sb0 + 1023u) & ~1023u;
    unsigned char* smb = smraw + (sb - sb0);

    const int nblk = blockIdx.x;
    const int m0 = blockIdx.y << 7;
    const int tid = threadIdx.x;
    const int lane = tid & 31, wid = tid >> 5;
    const int wm = wid >> 2, wn = wid & 3;

    float* biasf = (float*)(smb + 65536);
    if (tid < 32)
        *(float4*)(biasf + (tid << 2)) = *(const float4*)(fc1_b + (nblk << 7) + (tid << 2));

    auto issue = [&](int kcx, int stg) {
        const uint32_t sbase = sb + (uint32_t)stg * 32768u;
        const uint4* srcA = (const uint4*)g_fcA;
#pragma unroll
        for (int i = 0; i < 4; i++) {
            int u = tid + (i << 8);
            int r = u >> 3, c16 = u & 7;
            uint32_t dst = sbase + swz128((uint32_t)r * 128u + ((uint32_t)c16 << 4));
            cpasync16(dst, &srcA[(size_t)(m0 + r) * 64 + (kcx << 3) + c16]);
        }
        const unsigned char* src = &g_fc1Bsw[nblk][kcx][0];
#pragma unroll
        for (int i = 0; i < 4; i++) {
            uint32_t o = ((uint32_t)tid + ((uint32_t)i << 8)) << 4;
            cpasync16(sbase + 16384u + o, src + o);
        }
        CPASYNC_COMMIT();
    };

    float acc[4][4][4];
#pragma unroll
    for (int a = 0; a < 4; a++)
#pragma unroll
        for (int b = 0; b < 4; b++)
#pragma unroll
            for (int c = 0; c < 4; c++) acc[a][b][c] = 0.f;

    const int arow = (wm << 6) + (lane & 15);
    const int atop = (lane >> 4) << 4;
    const int brow = (wn << 5) + (lane & 7) + ((lane & 16) ? 8 : 0);
    const int btop = (lane & 8) ? 16 : 0;

    issue(0, 0);
    for (int kc = 0; kc < 8; kc++) {
        const int stg = kc & 1;
        if (kc < 7) { issue(kc + 1, stg ^ 1); CPASYNC_WAIT_1(); }
        else        { CPASYNC_WAIT_0(); }
        __syncthreads();

        const uint32_t aB = sb + (uint32_t)stg * 32768u, bB = aB + 16384u;
#pragma unroll
        for (int ks = 0; ks < 4; ks++) {
            const uint32_t kbyte = (uint32_t)ks << 5;
            uint32_t ah[4][4], bh[8];
#pragma unroll
            for (int mi = 0; mi < 4; mi++) {
                uint32_t off = swz128((uint32_t)(arow + mi * 16) * 128u + kbyte + (uint32_t)atop);
                ldsm4(ah[mi], aB + off);
            }
#pragma unroll
            for (int bi = 0; bi < 2; bi++) {
                uint32_t off = swz128((uint32_t)(brow + bi * 16) * 128u + kbyte + (uint32_t)btop);
                ldsm4(bh + bi * 4, bB + off);
            }
#pragma unroll
            for (int mi = 0; mi < 4; mi++)
#pragma unroll
                for (int ni = 0; ni < 4; ni++)
                    mma_f16(acc[mi][ni], ah[mi], bh + ni * 2);
        }
        __syncthreads();
    }

    // epilogue: bias + leaky, direct register store
#pragma unroll
    for (int mi = 0; mi < 4; mi++) {
        int r0 = m0 + (wm << 6) + mi * 16 + (lane >> 2);
#pragma unroll
        for (int ni = 0; ni < 4; ni++) {
            int cl = (wn << 5) + ni * 8 + ((lane & 3) << 1);
            int c0 = (nblk << 7) + cl;
            float b0 = biasf[cl], b1 = biasf[cl + 1];
            *(float2*)(g_fc1 + (size_t)r0 * FHh + c0) =
                make_float2(leakyf_(acc[mi][ni][0] + b0), leakyf_(acc[mi][ni][1] + b1));
            *(float2*)(g_fc1 + (size_t)(r0 + 8) * FHh + c0) =
                make_float2(leakyf_(acc[mi][ni][2] + b0), leakyf_(acc[mi][ni][3] + b1));
        }
    }
}

// ---------------------------------------------------------------------------
// fc2: out[n] = sigmoid( g_fc1[n] . fc2_w + fc2_b )
// ---------------------------------------------------------------------------
__global__ void __launch_bounds__(128) fc2_kernel(const float* __restrict__ w,
                                                  const float* __restrict__ b,
                                                  float* __restrict__ out)
{
    const int n = blockIdx.x;
    const int t = threadIdx.x;
    const float4 a = ((const float4*)(g_fc1 + (size_t)n * FHh))[t];
    const float4 wv = ((const float4*)w)[t];
    float s = a.x * wv.x + a.y * wv.y + a.z * wv.z + a.w * wv.w;
#pragma unroll
    for (int o = 16; o > 0; o >>= 1) s += __shfl_xor_sync(0xffffffffu, s, o);
    __shared__ float ws[4];
    if ((t & 31) == 0) ws[t >> 5] = s;
    __syncthreads();
    if (t == 0) {
        const float tot = ws[0] + ws[1] + ws[2] + ws[3];
        out[n] = 1.0f / (1.0f + expf(-(tot + b[0])));
    }
}

// ---------------------------------------------------------------------------
extern "C" void kernel_launch(void* const* d_in, const int* in_sizes, int n_in,
                              void* d_out, int out_size)
{
    const int*   x      = (const int*)  d_in[0];
    const float* embed  = (const float*)d_in[1];
    const float* Wih_f  = (const float*)d_in[2];
    const float* Whh_f  = (const float*)d_in[3];
    const float* bih_f  = (const float*)d_in[4];
    const float* bhh_f  = (const float*)d_in[5];
    const float* Wih_b  = (const float*)d_in[6];
    const float* Whh_b  = (const float*)d_in[7];
    const float* bih_b  = (const float*)d_in[8];
    const float* bhh_b  = (const float*)d_in[9];
    const float* fc1_w  = (const float*)d_in[10];
    const float* fc1_b  = (const float*)d_in[11];
    const float* fc2_w  = (const float*)d_in[12];
    const float* fc2_b  = (const float*)d_in[13];
    float* out = (float*)d_out;

    cudaFuncSetAttribute(gates_mma, cudaFuncAttributeMaxDynamicSharedMemorySize, SB_SMEM);
    cudaFuncSetAttribute(fc1_mma,   cudaFuncAttributeMaxDynamicSharedMemorySize, SB_SMEM);
    cudaFuncSetAttribute(pv_mma,    cudaFuncAttributeMaxDynamicSharedMemorySize, PV_SMEM);

    prep_all<<<640, 256>>>(Whh_f, Whh_b, Wih_f, Wih_b, fc1_w,
                           bih_f, bhh_f, bih_b, bhh_b);
    pv_mma<<<dim3(8, 63, 2), 256, PV_SMEM>>>(embed);

    // step 0 (h0 = 0): exact elementwise init, no GEMM
    gates_init<<<4096, 256>>>(x);

    for (int k = 1; k <= WSw; k++) {
        gates_mma<<<dim3(8, NTOK / 128, 2), 256, SB_SMEM>>>(x, k);
    }

    fc1_mma<<<dim3(4, 128), 256, SB_SMEM>>>(fc1_b);
    fc2_kernel<<<NTOK, 128>>>(fc2_w, fc2_b, out);
}

// round 15
// speedup vs baseline: 1.2351x; 1.2351x over previous
#include <cuda_runtime.h>
#include <cuda_fp16.h>
#include <math.h>
#include <stdint.h>

#define Bb   16
#define Ss   1024
#define Ee   256
#define Hh   256
#define FHh  512
#define Vv   8000
#define WSw  5
#define NTOK (Bb*Ss)     /* 16384 */
#define G4H  (4*Hh)      /* 1024  */

// ---------------- scratch (device globals; no dynamic allocation) ----------
__device__ float g_PVp[2][(size_t)Vv * G4H];            // permuted-col input projections
__device__ __half g_hA[2][2][(size_t)NTOK * Hh];        // [dir][pingpong] h as fp16
__device__ float g_cst[2][(size_t)NTOK * Hh];           // [dir] c state
__device__ __half g_fcA[(size_t)NTOK * FHh];            // leaky(h) concat, fc1 A (fp16)
__device__ float g_fc1[(size_t)NTOK * FHh];
// fp16 weights, col-permuted, pre-swizzled tiles (128 rows x 64 k = 16KB)
__device__ unsigned char g_Bsw[2][8][4][16384];         // Whh  [dir][nblk][kc]
__device__ unsigned char g_BswIH[2][8][4][16384];       // Wih  [dir][nblk][kc]
__device__ unsigned char g_fc1Bsw[4][8][16384];         // fc1_w [nblk][kc]
__device__ float g_bsum[2][G4H];                        // permuted bih+bhh

// fast activations: __expf-based, rel err ~2^-21 (safe vs 1e-3 budget)
__device__ __forceinline__ float sigf_(float x) {
    return __fdividef(1.0f, 1.0f + __expf(-x));
}
__device__ __forceinline__ float tanhf_(float x) {
    x = fminf(fmaxf(x, -15.0f), 15.0f);
    float e = __expf(2.0f * x);
    return __fdividef(e - 1.0f, e + 1.0f);
}
__device__ __forceinline__ float leakyf_(float x)   { return x > 0.0f ? x : 0.01f * x; }
__device__ __forceinline__ uint32_t swz128(uint32_t off) { return off ^ ((off >> 3) & 0x70); }
__device__ __forceinline__ uint32_t smem_u32(const void* p) {
    uint32_t a;
    asm("{ .reg .u64 t; cvta.to.shared.u64 t, %1; cvt.u32.u64 %0, t; }" : "=r"(a) : "l"(p));
    return a;
}
__device__ __forceinline__ void ldsm4(uint32_t* r, uint32_t addr) {
    asm volatile("ldmatrix.sync.aligned.m8n8.x4.shared.b16 {%0,%1,%2,%3}, [%4];"
        : "=r"(r[0]), "=r"(r[1]), "=r"(r[2]), "=r"(r[3]) : "r"(addr));
}
__device__ __forceinline__ void mma_f16(float* d, const uint32_t* a, const uint32_t* b) {
    asm volatile("mma.sync.aligned.m16n8k16.row.col.f32.f16.f16.f32 "
        "{%0,%1,%2,%3}, {%4,%5,%6,%7}, {%8,%9}, {%0,%1,%2,%3};"
        : "+f"(d[0]), "+f"(d[1]), "+f"(d[2]), "+f"(d[3])
        : "r"(a[0]), "r"(a[1]), "r"(a[2]), "r"(a[3]), "r"(b[0]), "r"(b[1]));
}
__device__ __forceinline__ void cpasync16(uint32_t dst, const void* src) {
    asm volatile("cp.async.cg.shared.global [%0], [%1], 16;" :: "r"(dst), "l"(src));
}
#define CPASYNC_COMMIT() asm volatile("cp.async.commit_group;" ::: "memory")
#define CPASYNC_WAIT_0() asm volatile("cp.async.wait_group 0;" ::: "memory")

__device__ __forceinline__ uint32_t packh(__half a, __half b) {
    unsigned short ua = *(unsigned short*)&a, ub = *(unsigned short*)&b;
    return (uint32_t)ua | ((uint32_t)ub << 16);
}

// permutation: unit u (0..255), gate g (0..3) -> permuted col
// p = (u>>3)*32 + ((u>>2)&1)*16 + (g>>1)*8 + (u&3)*2 + (g&1)
// => each mma-fragment thread owns complete gate quadruples of 2 units/row.
__device__ __host__ __forceinline__ int permcol(int u, int g) {
    return ((u >> 3) << 5) | (((u >> 2) & 1) << 4) | ((g >> 1) << 3) | ((u & 3) << 1) | (g & 1);
}

#define PV_SMEM  (1024 + 32768 + 512)
#define SB_SMEM  (1024 + 32768 + 512)

// ---------------------------------------------------------------------------
// prep_all: blocks [0,256) Whh (+bias), [256,512) Wih, [512,640) fc1_w.
// fp16 RN, permutation permcol() for Whh/Wih, pre-swizzled.
// ---------------------------------------------------------------------------
__global__ void __launch_bounds__(256) prep_all(const float* __restrict__ Whf, const float* __restrict__ Whb,
                                                const float* __restrict__ Wif, const float* __restrict__ Wib,
                                                const float* __restrict__ fc1w,
                                                const float* __restrict__ bihf, const float* __restrict__ bhhf,
                                                const float* __restrict__ bihb, const float* __restrict__ bhhb)
{
    const int blk = blockIdx.x;
    const int tid = threadIdx.x;
    if (blk < 512) {
        const int sect = blk >> 8;                       // 0 = Whh, 1 = Wih
        int idx = (blk & 255) * 256 + tid;               // 65536 per section
        int dir = idx >> 15;
        int r = idx & 32767;
        int n = r >> 5;
        int k8 = (r & 31) << 3;
        const float* W = sect ? (dir ? Wib : Wif) : (dir ? Whb : Whf);
        int unit = n & 255, gate = n >> 8;
        int p = permcol(unit, gate);
        int nblk = p >> 7, prow = p & 127;
        float4 v0 = *(const float4*)(W + (size_t)n * Hh + k8);
        float4 v1 = *(const float4*)(W + (size_t)n * Hh + k8 + 4);
        float vals[8] = {v0.x, v0.y, v0.z, v0.w, v1.x, v1.y, v1.z, v1.w};
#pragma unroll
        for (int j = 0; j < 8; j++) {
            int k = k8 + j;
            int kc = k >> 6, kb = k & 63;
            uint32_t off = swz128((uint32_t)prow * 128u + (uint32_t)kb * 2u);
            __half hv = __float2half(vals[j]);
            if (sect == 0) *(__half*)(&g_Bsw[dir][nblk][kc][off]) = hv;
            else           *(__half*)(&g_BswIH[dir][nblk][kc][off]) = hv;
        }
        if (sect == 0 && k8 == 0) {
            const float* bi = dir ? bihb : bihf;
            const float* bh = dir ? bhhb : bhhf;
            g_bsum[dir][p] = bi[n] + bh[n];
        }
    } else {
        int idx = (blk - 512) * 256 + tid;               // 32768 threads
        int n = idx >> 6;                                // 0..511
        int k8 = (idx & 63) << 3;
        int nblk = n >> 7, prow = n & 127;
        float4 v0 = *(const float4*)(fc1w + (size_t)n * FHh + k8);
        float4 v1 = *(const float4*)(fc1w + (size_t)n * FHh + k8 + 4);
        float vals[8] = {v0.x, v0.y, v0.z, v0.w, v1.x, v1.y, v1.z, v1.w};
#pragma unroll
        for (int j = 0; j < 8; j++) {
            int k = k8 + j;
            int kc = k >> 6, kb = k & 63;
            uint32_t off = swz128((uint32_t)prow * 128u + (uint32_t)kb * 2u);
            *(__half*)(&g_fc1Bsw[nblk][kc][off]) = __float2half(vals[j]);
        }
    }
}

// ---------------------------------------------------------------------------
// pv_mma: PVp[dir] = embed(row0=0) @ Wih^T (permuted cols inherited from
// the prepped Wih), fp16 1-term. smem: A 16KB | B 16KB.
// ---------------------------------------------------------------------------
__global__ void __launch_bounds__(256) pv_mma(const float* __restrict__ embed)
{
    extern __shared__ unsigned char smraw[];
    uint32_t sb0 = smem_u32(smraw);
    uint32_t sb = (sb0 + 1023u) & ~1023u;
    unsigned char* smb = smraw + (sb - sb0);

    const int dir = blockIdx.z;
    const int nblk = blockIdx.x;
    const int m0 = blockIdx.y << 7;
    const int tid = threadIdx.x;
    const int lane = tid & 31, wid = tid >> 5;
    const int wm = wid >> 2, wn = wid & 3;

    float acc[4][4][4];
#pragma unroll
    for (int a = 0; a < 4; a++)
#pragma unroll
        for (int b = 0; b < 4; b++)
#pragma unroll
            for (int c = 0; c < 4; c++) acc[a][b][c] = 0.f;

    const uint32_t aBase = sb, bBase = sb + 16384u;
    const int arow = (wm << 6) + (lane & 15);
    const int atop = (lane >> 4) << 4;
    const int brow = (wn << 5) + (lane & 7) + ((lane & 16) ? 8 : 0);
    const int btop = (lane & 8) ? 16 : 0;

    for (int kc = 0; kc < 4; kc++) {
#pragma unroll
        for (int i = 0; i < 4; i++) {
            int u = tid + (i << 8);
            int r = u >> 3, c8 = u & 7;
            int g = m0 + r;
            float vals[8];
            if (g == 0 || g >= Vv) {
#pragma unroll
                for (int j = 0; j < 8; j++) vals[j] = 0.f;
            } else {
                float4 v0 = *(const float4*)(embed + (size_t)g * Ee + (kc << 6) + (c8 << 3));
                float4 v1 = *(const float4*)(embed + (size_t)g * Ee + (kc << 6) + (c8 << 3) + 4);
                vals[0] = v0.x; vals[1] = v0.y; vals[2] = v0.z; vals[3] = v0.w;
                vals[4] = v1.x; vals[5] = v1.y; vals[6] = v1.z; vals[7] = v1.w;
            }
            uint4 hv;
            hv.x = packh(__float2half(vals[0]), __float2half(vals[1]));
            hv.y = packh(__float2half(vals[2]), __float2half(vals[3]));
            hv.z = packh(__float2half(vals[4]), __float2half(vals[5]));
            hv.w = packh(__float2half(vals[6]), __float2half(vals[7]));
            *(uint4*)(smb + swz128((uint32_t)r * 128u + ((uint32_t)c8 << 4))) = hv;
        }
        {
            const uint4* src = (const uint4*)&g_BswIH[dir][nblk][kc][0];
            uint4* dst = (uint4*)(smb + 16384);
#pragma unroll
            for (int i = 0; i < 4; i++) dst[tid + (i << 8)] = src[tid + (i << 8)];
        }
        __syncthreads();

#pragma unroll
        for (int ks = 0; ks < 4; ks++) {
            const uint32_t kbyte = (uint32_t)ks << 5;
            uint32_t ah[4][4], bh[8];
#pragma unroll
            for (int mi = 0; mi < 4; mi++) {
                uint32_t off = swz128((uint32_t)(arow + mi * 16) * 128u + kbyte + (uint32_t)atop);
                ldsm4(ah[mi], aBase + off);
            }
#pragma unroll
            for (int bi = 0; bi < 2; bi++) {
                uint32_t off = swz128((uint32_t)(brow + bi * 16) * 128u + kbyte + (uint32_t)btop);
                ldsm4(bh + bi * 4, bBase + off);
            }
#pragma unroll
            for (int mi = 0; mi < 4; mi++)
#pragma unroll
                for (int ni = 0; ni < 4; ni++)
                    mma_f16(acc[mi][ni], ah[mi], bh + ni * 2);
        }
        __syncthreads();
    }

    float* out = g_PVp[dir];
#pragma unroll
    for (int mi = 0; mi < 4; mi++) {
        int r0 = m0 + (wm << 6) + mi * 16 + (lane >> 2);
#pragma unroll
        for (int ni = 0; ni < 4; ni++) {
            int c0 = (nblk << 7) + (wn << 5) + ni * 8 + ((lane & 3) << 1);
            if (r0 < Vv)
                *(float2*)(out + (size_t)r0 * G4H + c0) = make_float2(acc[mi][ni][0], acc[mi][ni][1]);
            if (r0 + 8 < Vv)
                *(float2*)(out + (size_t)(r0 + 8) * G4H + c0) = make_float2(acc[mi][ni][2], acc[mi][ni][3]);
        }
    }
}

// ---------------------------------------------------------------------------
// gates_init: step 0 exactly (h0 = c0 = 0). One thread = one (row, dir,
// 8-unit group); FULL coverage: 2 dirs x 16384 rows x 32 groups.
// ---------------------------------------------------------------------------
__global__ void __launch_bounds__(256) gates_init(const int* __restrict__ x)
{
    int idx = blockIdx.x * 256 + threadIdx.x;          // 1,048,576 threads
    int dir = idx >> 19;
    int r = idx & 524287;
    int row = r >> 5;
    int g32 = r & 31;                                  // 8-unit group (0..31)
    int t = row & (Ss - 1), bidx = row >> 10;
    int tp = dir ? (t + WSw) : (t - WSw);
    bool valid = ((unsigned)tp < (unsigned)Ss);
    int tok = valid ? x[(bidx << 10) + tp] : 0;
    const float* pv = g_PVp[dir] + (size_t)tok * G4H + (g32 << 5);
    const float* bs = g_bsum[dir] + (g32 << 5);
    float* crow = g_cst[dir] + (size_t)row * Hh + (g32 << 3);
    __half* hrow = g_hA[dir][1] + (size_t)row * Hh + (g32 << 3);

    float c8[8], h8[8];
#pragma unroll
    for (int u = 0; u < 8; u++) {
        int q = u & 3, tt = u >> 2;
        int ic = (tt << 4) + (q << 1);
        float gi = bs[ic], gg = bs[ic + 8], go = bs[ic + 9];
        if (valid) {
            gi += pv[ic]; gg += pv[ic + 8]; go += pv[ic + 9];
        }
        float cn = sigf_(gi) * tanhf_(gg);
        c8[u] = cn;
        h8[u] = sigf_(go) * tanhf_(cn);
    }
    *(float4*)crow       = make_float4(c8[0], c8[1], c8[2], c8[3]);
    *(float4*)(crow + 4) = make_float4(c8[4], c8[5], c8[6], c8[7]);
    uint4 hw;
    hw.x = packh(__float2half(h8[0]), __float2half(h8[1]));
    hw.y = packh(__float2half(h8[2]), __float2half(h8[3]));
    hw.z = packh(__float2half(h8[4]), __float2half(h8[5]));
    hw.w = packh(__float2half(h8[6]), __float2half(h8[7]));
    *(uint4*)hrow = hw;
}

// ---------------------------------------------------------------------------
// gates_mma: steps 1..5, both dirs. fp16 1-term, single 32KB stage, 2 CTAs/SM,
// register-direct fused LSTM epilogue (permcol layout).
// ---------------------------------------------------------------------------
__global__ void __launch_bounds__(256, 2) gates_mma(const int* __restrict__ x, int step)
{
    extern __shared__ unsigned char smraw[];
    uint32_t sb0 = smem_u32(smraw);
    uint32_t sb = (sb0 + 1023u) & ~1023u;
    unsigned char* smb = smraw + (sb - sb0);

    const int dir = blockIdx.z;
    const int nblk = blockIdx.x;
    const int m0 = blockIdx.y << 7;
    const int tid = threadIdx.x;
    const int lane = tid & 31, wid = tid >> 5;
    const int wm = wid >> 2, wn = wid & 3;
    const int buf = step & 1, nbuf = buf ^ 1;

    float* biasf = (float*)(smb + 32768);
    if (tid < 32)
        *(float4*)(biasf + (tid << 2)) = *(const float4*)(g_bsum[dir] + (nblk << 7) + (tid << 2));

    const uint4* srcA = (const uint4*)g_hA[dir][buf];

    float acc[4][4][4];
#pragma unroll
    for (int a = 0; a < 4; a++)
#pragma unroll
        for (int b = 0; b < 4; b++)
#pragma unroll
            for (int c = 0; c < 4; c++) acc[a][b][c] = 0.f;

    const int arow = (wm << 6) + (lane & 15);
    const int atop = (lane >> 4) << 4;
    const int brow = (wn << 5) + (lane & 7) + ((lane & 16) ? 8 : 0);
    const int btop = (lane & 8) ? 16 : 0;

    for (int kc = 0; kc < 4; kc++) {
        // A: fp16 plane, 16KB
#pragma unroll
        for (int i = 0; i < 4; i++) {
            int u = tid + (i << 8);
            int r = u >> 3, c16 = u & 7;
            uint32_t dst = sb + swz128((uint32_t)r * 128u + ((uint32_t)c16 << 4));
            cpasync16(dst, &srcA[(size_t)(m0 + r) * 32 + (kc << 3) + c16]);
        }
        // B: 16KB
        {
            const unsigned char* src = &g_Bsw[dir][nblk][kc][0];
#pragma unroll
            for (int i = 0; i < 4; i++) {
                uint32_t o = ((uint32_t)tid + ((uint32_t)i << 8)) << 4;
                cpasync16(sb + 16384u + o, src + o);
            }
        }
        CPASYNC_COMMIT();
        CPASYNC_WAIT_0();
        __syncthreads();

        const uint32_t aB = sb, bB = sb + 16384u;
#pragma unroll
        for (int ks = 0; ks < 4; ks++) {
            const uint32_t kbyte = (uint32_t)ks << 5;
            uint32_t ah[4][4], bh[8];
#pragma unroll
            for (int mi = 0; mi < 4; mi++) {
                uint32_t off = swz128((uint32_t)(arow + mi * 16) * 128u + kbyte + (uint32_t)atop);
                ldsm4(ah[mi], aB + off);
            }
#pragma unroll
            for (int bi = 0; bi < 2; bi++) {
                uint32_t off = swz128((uint32_t)(brow + bi * 16) * 128u + kbyte + (uint32_t)btop);
                ldsm4(bh + bi * 4, bB + off);
            }
#pragma unroll
            for (int mi = 0; mi < 4; mi++)
#pragma unroll
                for (int ni = 0; ni < 4; ni++)
                    mma_f16(acc[mi][ni], ah[mi], bh + ni * 2);
        }
        if (kc < 3) __syncthreads();
    }

    // ---- register-direct fused epilogue (no smem staging) ----
    const int q = lane & 3;
    const int rbl = (wm << 6) + (lane >> 2);
    const int ug0 = ((nblk << 2) + wn) << 3;           // unit_global base (8 units)
    const float* bs = biasf + (wn << 5);
    const bool finalstep = (step == WSw);

#pragma unroll
    for (int mi = 0; mi < 4; mi++) {
#pragma unroll
        for (int t2 = 0; t2 < 2; t2++) {
            const int row = m0 + rbl + mi * 16 + (t2 << 3);
            const int t = row & (Ss - 1), bidx = row >> 10;
            const int tp = dir ? (t + WSw - step) : (t - WSw + step);
            const bool valid = ((unsigned)tp < (unsigned)Ss);
            const int tok = valid ? x[(bidx << 10) + tp] : 0;
            const float* pvrow = g_PVp[dir] + (size_t)tok * G4H + (nblk << 7) + (wn << 5);
            float* crow = g_cst[dir] + (size_t)row * Hh + ug0;
            __half* hrow = g_hA[dir][nbuf] + (size_t)row * Hh + ug0;
            __half* frow = g_fcA + (size_t)row * FHh + dir * Hh + ug0;
#pragma unroll
            for (int tt = 0; tt < 2; tt++) {
                float gi = acc[mi][2 * tt][2 * t2];
                float gf = acc[mi][2 * tt][2 * t2 + 1];
                float gg = acc[mi][2 * tt + 1][2 * t2];
                float go = acc[mi][2 * tt + 1][2 * t2 + 1];
                const int ic = (tt << 4) + (q << 1);
                gi += bs[ic]; gf += bs[ic + 1]; gg += bs[ic + 8]; go += bs[ic + 9];
                if (valid) {
                    float2 pif = *(const float2*)(pvrow + ic);
                    float2 pgo = *(const float2*)(pvrow + ic + 8);
                    gi += pif.x; gf += pif.y; gg += pgo.x; go += pgo.y;
                }
                const int u = q + (tt << 2);
                float cv = crow[u];
                float cn = sigf_(gf) * cv + sigf_(gi) * tanhf_(gg);
                crow[u] = cn;
                float hv = sigf_(go) * tanhf_(cn);
                hrow[u] = __float2half(hv);
                if (finalstep) frow[u] = __float2half(leakyf_(hv));
            }
        }
    }
}

// ---------------------------------------------------------------------------
// fc1_mma: g_fc1 = leaky( fcA @ fc1_w^T + fc1_b ). fp16 1-term, single stage,
// 2 CTAs/SM. grid (4 nblk, 128 mtile). K=512 in 8 chunks.
// ---------------------------------------------------------------------------
__global__ void __launch_bounds__(256, 2) fc1_mma(const float* __restrict__ fc1_b)
{
    extern __shared__ unsigned char smraw[];
    uint32_t sb0 = smem_u32(smraw);
    uint32_t sb = (sb0 + 1023u) & ~1023u;
    unsigned char* smb = smraw + (sb - sb0);

    const int nblk = blockIdx.x;
    const int m0 = blockIdx.y << 7;
    const int tid = threadIdx.x;
    const int lane = tid & 31, wid = tid >> 5;
    const int wm = wid >> 2, wn = wid & 3;

    float* biasf = (float*)(smb + 32768);
    if (tid < 32)
        *(float4*)(biasf + (tid << 2)) = *(const float4*)(fc1_b + (nblk << 7) + (tid << 2));

    float acc[4][4][4];
#pragma unroll
    for (int a = 0; a < 4; a++)
#pragma unroll
        for (int b = 0; b < 4; b++)
#pragma unroll
            for (int c = 0; c < 4; c++) acc[a][b][c] = 0.f;

    const int arow = (wm << 6) + (lane & 15);
    const int atop = (lane >> 4) << 4;
    const int brow = (wn << 5) + (lane & 7) + ((lane & 16) ? 8 : 0);
    const int btop = (lane & 8) ? 16 : 0;

    for (int kc = 0; kc < 8; kc++) {
        const uint4* srcA = (const uint4*)g_fcA;
#pragma unroll
        for (int i = 0; i < 4; i++) {
            int u = tid + (i << 8);
            int r = u >> 3, c16 = u & 7;
            uint32_t dst = sb + swz128((uint32_t)r * 128u + ((uint32_t)c16 << 4));
            cpasync16(dst, &srcA[(size_t)(m0 + r) * 64 + (kc << 3) + c16]);
        }
        {
            const unsigned char* src = &g_fc1Bsw[nblk][kc][0];
#pragma unroll
            for (int i = 0; i < 4; i++) {
                uint32_t o = ((uint32_t)tid + ((uint32_t)i << 8)) << 4;
                cpasync16(sb + 16384u + o, src + o);
            }
        }
        CPASYNC_COMMIT();
        CPASYNC_WAIT_0();
        __syncthreads();

        const uint32_t aB = sb, bB = sb + 16384u;
#pragma unroll
        for (int ks = 0; ks < 4; ks++) {
            const uint32_t kbyte = (uint32_t)ks << 5;
            uint32_t ah[4][4], bh[8];
#pragma unroll
            for (int mi = 0; mi < 4; mi++) {
                uint32_t off = swz128((uint32_t)(arow + mi * 16) * 128u + kbyte + (uint32_t)atop);
                ldsm4(ah[mi], aB + off);
            }
#pragma unroll
            for (int bi = 0; bi < 2; bi++) {
                uint32_t off = swz128((uint32_t)(brow + bi * 16) * 128u + kbyte + (uint32_t)btop);
                ldsm4(bh + bi * 4, bB + off);
            }
#pragma unroll
            for (int mi = 0; mi < 4; mi++)
#pragma unroll
                for (int ni = 0; ni < 4; ni++)
                    mma_f16(acc[mi][ni], ah[mi], bh + ni * 2);
        }
        if (kc < 7) __syncthreads();
    }

    // epilogue: bias + leaky, direct register store
#pragma unroll
    for (int mi = 0; mi < 4; mi++) {
        int r0 = m0 + (wm << 6) + mi * 16 + (lane >> 2);
#pragma unroll
        for (int ni = 0; ni < 4; ni++) {
            int cl = (wn << 5) + ni * 8 + ((lane & 3) << 1);
            int c0 = (nblk << 7) + cl;
            float b0 = biasf[cl], b1 = biasf[cl + 1];
            *(float2*)(g_fc1 + (size_t)r0 * FHh + c0) =
                make_float2(leakyf_(acc[mi][ni][0] + b0), leakyf_(acc[mi][ni][1] + b1));
            *(float2*)(g_fc1 + (size_t)(r0 + 8) * FHh + c0) =
                make_float2(leakyf_(acc[mi][ni][2] + b0), leakyf_(acc[mi][ni][3] + b1));
        }
    }
}

// ---------------------------------------------------------------------------
// fc2: out[n] = sigmoid( g_fc1[n] . fc2_w + fc2_b )
// ---------------------------------------------------------------------------
__global__ void __launch_bounds__(128) fc2_kernel(const float* __restrict__ w,
                                                  const float* __restrict__ b,
                                                  float* __restrict__ out)
{
    const int n = blockIdx.x;
    const int t = threadIdx.x;
    const float4 a = ((const float4*)(g_fc1 + (size_t)n * FHh))[t];
    const float4 wv = ((const float4*)w)[t];
    float s = a.x * wv.x + a.y * wv.y + a.z * wv.z + a.w * wv.w;
#pragma unroll
    for (int o = 16; o > 0; o >>= 1) s += __shfl_xor_sync(0xffffffffu, s, o);
    __shared__ float ws[4];
    if ((t & 31) == 0) ws[t >> 5] = s;
    __syncthreads();
    if (t == 0) {
        const float tot = ws[0] + ws[1] + ws[2] + ws[3];
        out[n] = sigf_(tot + b[0]);
    }
}

// ---------------------------------------------------------------------------
extern "C" void kernel_launch(void* const* d_in, const int* in_sizes, int n_in,
                              void* d_out, int out_size)
{
    const int*   x      = (const int*)  d_in[0];
    const float* embed  = (const float*)d_in[1];
    const float* Wih_f  = (const float*)d_in[2];
    const float* Whh_f  = (const float*)d_in[3];
    const float* bih_f  = (const float*)d_in[4];
    const float* bhh_f  = (const float*)d_in[5];
    const float* Wih_b  = (const float*)d_in[6];
    const float* Whh_b  = (const float*)d_in[7];
    const float* bih_b  = (const float*)d_in[8];
    const float* bhh_b  = (const float*)d_in[9];
    const float* fc1_w  = (const float*)d_in[10];
    const float* fc1_b  = (const float*)d_in[11];
    const float* fc2_w  = (const float*)d_in[12];
    const float* fc2_b  = (const float*)d_in[13];
    float* out = (float*)d_out;

    cudaFuncSetAttribute(gates_mma, cudaFuncAttributeMaxDynamicSharedMemorySize, SB_SMEM);
    cudaFuncSetAttribute(fc1_mma,   cudaFuncAttributeMaxDynamicSharedMemorySize, SB_SMEM);
    cudaFuncSetAttribute(pv_mma,    cudaFuncAttributeMaxDynamicSharedMemorySize, PV_SMEM);

    prep_all<<<640, 256>>>(Whh_f, Whh_b, Wih_f, Wih_b, fc1_w,
                           bih_f, bhh_f, bih_b, bhh_b);
    pv_mma<<<dim3(8, 63, 2), 256, PV_SMEM>>>(embed);

    // step 0 (h0 = 0): exact elementwise init, no GEMM (full 256-unit coverage)
    gates_init<<<4096, 256>>>(x);

    for (int k = 1; k <= WSw; k++) {
        gates_mma<<<dim3(8, NTOK / 128, 2), 256, SB_SMEM>>>(x, k);
    }

    fc1_mma<<<dim3(4, 128), 256, SB_SMEM>>>(fc1_b);
    fc2_kernel<<<NTOK, 128>>>(fc2_w, fc2_b, out);
}

// round 16
// speedup vs baseline: 1.3385x; 1.0838x over previous
#include <cuda_runtime.h>
#include <cuda_fp16.h>
#include <math.h>
#include <stdint.h>

#define Bb   16
#define Ss   1024
#define Ee   256
#define Hh   256
#define FHh  512
#define Vv   8000
#define WSw  5
#define NTOK (Bb*Ss)     /* 16384 */
#define G4H  (4*Hh)      /* 1024  */

// ---------------- scratch (device globals; no dynamic allocation) ----------
__device__ float g_PVp[2][(size_t)Vv * G4H];            // permuted-col input projections
__device__ __half g_hA[2][2][(size_t)NTOK * Hh];        // [dir][pingpong] h as fp16
__device__ float g_cst[2][(size_t)NTOK * Hh];           // [dir] c state
__device__ __half g_fcA[(size_t)NTOK * FHh];            // leaky(h) concat, fc1 A (fp16)
__device__ float g_dot[NTOK];                           // fc2 partial dots
// fp16 weights, col-permuted, pre-swizzled tiles (128 rows x 64 k = 16KB)
__device__ unsigned char g_Bsw[2][8][4][16384];         // Whh  [dir][nblk][kc]
__device__ unsigned char g_BswIH[2][8][4][16384];       // Wih  [dir][nblk][kc]
__device__ unsigned char g_fc1Bsw[4][8][16384];         // fc1_w [nblk][kc]
__device__ float g_bsum[2][G4H];                        // permuted bih+bhh

// fast activations: __expf-based, rel err ~2^-21 (safe vs 1e-3 budget)
__device__ __forceinline__ float sigf_(float x) {
    return __fdividef(1.0f, 1.0f + __expf(-x));
}
__device__ __forceinline__ float tanhf_(float x) {
    x = fminf(fmaxf(x, -15.0f), 15.0f);
    float e = __expf(2.0f * x);
    return __fdividef(e - 1.0f, e + 1.0f);
}
__device__ __forceinline__ float leakyf_(float x)   { return x > 0.0f ? x : 0.01f * x; }
__device__ __forceinline__ uint32_t swz128(uint32_t off) { return off ^ ((off >> 3) & 0x70); }
__device__ __forceinline__ uint32_t smem_u32(const void* p) {
    uint32_t a;
    asm("{ .reg .u64 t; cvta.to.shared.u64 t, %1; cvt.u32.u64 %0, t; }" : "=r"(a) : "l"(p));
    return a;
}
__device__ __forceinline__ void ldsm4(uint32_t* r, uint32_t addr) {
    asm volatile("ldmatrix.sync.aligned.m8n8.x4.shared.b16 {%0,%1,%2,%3}, [%4];"
        : "=r"(r[0]), "=r"(r[1]), "=r"(r[2]), "=r"(r[3]) : "r"(addr));
}
__device__ __forceinline__ void mma_f16(float* d, const uint32_t* a, const uint32_t* b) {
    asm volatile("mma.sync.aligned.m16n8k16.row.col.f32.f16.f16.f32 "
        "{%0,%1,%2,%3}, {%4,%5,%6,%7}, {%8,%9}, {%0,%1,%2,%3};"
        : "+f"(d[0]), "+f"(d[1]), "+f"(d[2]), "+f"(d[3])
        : "r"(a[0]), "r"(a[1]), "r"(a[2]), "r"(a[3]), "r"(b[0]), "r"(b[1]));
}
__device__ __forceinline__ void cpasync16(uint32_t dst, const void* src) {
    asm volatile("cp.async.cg.shared.global [%0], [%1], 16;" :: "r"(dst), "l"(src));
}
#define CPASYNC_COMMIT() asm volatile("cp.async.commit_group;" ::: "memory")
#define CPASYNC_WAIT_0() asm volatile("cp.async.wait_group 0;" ::: "memory")

__device__ __forceinline__ uint32_t packh(__half a, __half b) {
    unsigned short ua = *(unsigned short*)&a, ub = *(unsigned short*)&b;
    return (uint32_t)ua | ((uint32_t)ub << 16);
}

// permutation: unit u (0..255), gate g (0..3) -> permuted col
// p = (u>>3)*32 + ((u>>2)&1)*16 + (g>>1)*8 + (u&3)*2 + (g&1)
__device__ __host__ __forceinline__ int permcol(int u, int g) {
    return ((u >> 3) << 5) | (((u >> 2) & 1) << 4) | ((g >> 1) << 3) | ((u & 3) << 1) | (g & 1);
}

#define PV_SMEM  (1024 + 32768 + 512)
#define SB_SMEM  (1024 + 32768 + 512)

// ---------------------------------------------------------------------------
// prep_all: blocks [0,256) Whh (+bias), [256,512) Wih, [512,640) fc1_w.
// ---------------------------------------------------------------------------
__global__ void __launch_bounds__(256) prep_all(const float* __restrict__ Whf, const float* __restrict__ Whb,
                                                const float* __restrict__ Wif, const float* __restrict__ Wib,
                                                const float* __restrict__ fc1w,
                                                const float* __restrict__ bihf, const float* __restrict__ bhhf,
                                                const float* __restrict__ bihb, const float* __restrict__ bhhb)
{
    const int blk = blockIdx.x;
    const int tid = threadIdx.x;
    if (blk < 512) {
        const int sect = blk >> 8;                       // 0 = Whh, 1 = Wih
        int idx = (blk & 255) * 256 + tid;               // 65536 per section
        int dir = idx >> 15;
        int r = idx & 32767;
        int n = r >> 5;
        int k8 = (r & 31) << 3;
        const float* W = sect ? (dir ? Wib : Wif) : (dir ? Whb : Whf);
        int unit = n & 255, gate = n >> 8;
        int p = permcol(unit, gate);
        int nblk = p >> 7, prow = p & 127;
        float4 v0 = *(const float4*)(W + (size_t)n * Hh + k8);
        float4 v1 = *(const float4*)(W + (size_t)n * Hh + k8 + 4);
        float vals[8] = {v0.x, v0.y, v0.z, v0.w, v1.x, v1.y, v1.z, v1.w};
#pragma unroll
        for (int j = 0; j < 8; j++) {
            int k = k8 + j;
            int kc = k >> 6, kb = k & 63;
            uint32_t off = swz128((uint32_t)prow * 128u + (uint32_t)kb * 2u);
            __half hv = __float2half(vals[j]);
            if (sect == 0) *(__half*)(&g_Bsw[dir][nblk][kc][off]) = hv;
            else           *(__half*)(&g_BswIH[dir][nblk][kc][off]) = hv;
        }
        if (sect == 0 && k8 == 0) {
            const float* bi = dir ? bihb : bihf;
            const float* bh = dir ? bhhb : bhhf;
            g_bsum[dir][p] = bi[n] + bh[n];
        }
    } else {
        int idx = (blk - 512) * 256 + tid;               // 32768 threads
        int n = idx >> 6;                                // 0..511
        int k8 = (idx & 63) << 3;
        int nblk = n >> 7, prow = n & 127;
        float4 v0 = *(const float4*)(fc1w + (size_t)n * FHh + k8);
        float4 v1 = *(const float4*)(fc1w + (size_t)n * FHh + k8 + 4);
        float vals[8] = {v0.x, v0.y, v0.z, v0.w, v1.x, v1.y, v1.z, v1.w};
#pragma unroll
        for (int j = 0; j < 8; j++) {
            int k = k8 + j;
            int kc = k >> 6, kb = k & 63;
            uint32_t off = swz128((uint32_t)prow * 128u + (uint32_t)kb * 2u);
            *(__half*)(&g_fc1Bsw[nblk][kc][off]) = __float2half(vals[j]);
        }
    }
}

// ---------------------------------------------------------------------------
// pv_mma: PVp[dir] = embed(row0=0) @ Wih^T, fp16 1-term.
// ---------------------------------------------------------------------------
__global__ void __launch_bounds__(256) pv_mma(const float* __restrict__ embed)
{
    extern __shared__ unsigned char smraw[];
    uint32_t sb0 = smem_u32(smraw);
    uint32_t sb = (sb0 + 1023u) & ~1023u;
    unsigned char* smb = smraw + (sb - sb0);

    const int dir = blockIdx.z;
    const int nblk = blockIdx.x;
    const int m0 = blockIdx.y << 7;
    const int tid = threadIdx.x;
    const int lane = tid & 31, wid = tid >> 5;
    const int wm = wid >> 2, wn = wid & 3;

    float acc[4][4][4];
#pragma unroll
    for (int a = 0; a < 4; a++)
#pragma unroll
        for (int b = 0; b < 4; b++)
#pragma unroll
            for (int c = 0; c < 4; c++) acc[a][b][c] = 0.f;

    const uint32_t aBase = sb, bBase = sb + 16384u;
    const int arow = (wm << 6) + (lane & 15);
    const int atop = (lane >> 4) << 4;
    const int brow = (wn << 5) + (lane & 7) + ((lane & 16) ? 8 : 0);
    const int btop = (lane & 8) ? 16 : 0;

    for (int kc = 0; kc < 4; kc++) {
#pragma unroll
        for (int i = 0; i < 4; i++) {
            int u = tid + (i << 8);
            int r = u >> 3, c8 = u & 7;
            int g = m0 + r;
            float vals[8];
            if (g == 0 || g >= Vv) {
#pragma unroll
                for (int j = 0; j < 8; j++) vals[j] = 0.f;
            } else {
                float4 v0 = *(const float4*)(embed + (size_t)g * Ee + (kc << 6) + (c8 << 3));
                float4 v1 = *(const float4*)(embed + (size_t)g * Ee + (kc << 6) + (c8 << 3) + 4);
                vals[0] = v0.x; vals[1] = v0.y; vals[2] = v0.z; vals[3] = v0.w;
                vals[4] = v1.x; vals[5] = v1.y; vals[6] = v1.z; vals[7] = v1.w;
            }
            uint4 hv;
            hv.x = packh(__float2half(vals[0]), __float2half(vals[1]));
            hv.y = packh(__float2half(vals[2]), __float2half(vals[3]));
            hv.z = packh(__float2half(vals[4]), __float2half(vals[5]));
            hv.w = packh(__float2half(vals[6]), __float2half(vals[7]));
            *(uint4*)(smb + swz128((uint32_t)r * 128u + ((uint32_t)c8 << 4))) = hv;
        }
        {
            const uint4* src = (const uint4*)&g_BswIH[dir][nblk][kc][0];
            uint4* dst = (uint4*)(smb + 16384);
#pragma unroll
            for (int i = 0; i < 4; i++) dst[tid + (i << 8)] = src[tid + (i << 8)];
        }
        __syncthreads();

#pragma unroll
        for (int ks = 0; ks < 4; ks++) {
            const uint32_t kbyte = (uint32_t)ks << 5;
            uint32_t ah[4][4], bh[8];
#pragma unroll
            for (int mi = 0; mi < 4; mi++) {
                uint32_t off = swz128((uint32_t)(arow + mi * 16) * 128u + kbyte + (uint32_t)atop);
                ldsm4(ah[mi], aBase + off);
            }
#pragma unroll
            for (int bi = 0; bi < 2; bi++) {
                uint32_t off = swz128((uint32_t)(brow + bi * 16) * 128u + kbyte + (uint32_t)btop);
                ldsm4(bh + bi * 4, bBase + off);
            }
#pragma unroll
            for (int mi = 0; mi < 4; mi++)
#pragma unroll
                for (int ni = 0; ni < 4; ni++)
                    mma_f16(acc[mi][ni], ah[mi], bh + ni * 2);
        }
        __syncthreads();
    }

    float* out = g_PVp[dir];
#pragma unroll
    for (int mi = 0; mi < 4; mi++) {
        int r0 = m0 + (wm << 6) + mi * 16 + (lane >> 2);
#pragma unroll
        for (int ni = 0; ni < 4; ni++) {
            int c0 = (nblk << 7) + (wn << 5) + ni * 8 + ((lane & 3) << 1);
            if (r0 < Vv)
                *(float2*)(out + (size_t)r0 * G4H + c0) = make_float2(acc[mi][ni][0], acc[mi][ni][1]);
            if (r0 + 8 < Vv)
                *(float2*)(out + (size_t)(r0 + 8) * G4H + c0) = make_float2(acc[mi][ni][2], acc[mi][ni][3]);
        }
    }
}

// ---------------------------------------------------------------------------
// gates_init: step 0 exactly (h0 = c0 = 0). Vectorized loads (8 x float4).
// Full coverage: 2 dirs x 16384 rows x 32 groups of 8 units.
// ---------------------------------------------------------------------------
__global__ void __launch_bounds__(256) gates_init(const int* __restrict__ x)
{
    int idx = blockIdx.x * 256 + threadIdx.x;          // 1,048,576 threads
    int dir = idx >> 19;
    int r = idx & 524287;
    int row = r >> 5;
    int g32 = r & 31;                                  // 8-unit group (0..31)
    int t = row & (Ss - 1), bidx = row >> 10;
    int tp = dir ? (t + WSw) : (t - WSw);
    bool valid = ((unsigned)tp < (unsigned)Ss);
    int tok = valid ? x[(bidx << 10) + tp] : 0;
    const float4* pv4 = (const float4*)(g_PVp[dir] + (size_t)tok * G4H + (g32 << 5));
    const float4* bs4 = (const float4*)(g_bsum[dir] + (g32 << 5));
    float* crow = g_cst[dir] + (size_t)row * Hh + (g32 << 3);
    __half* hrow = g_hA[dir][1] + (size_t)row * Hh + (g32 << 3);

    float gv[32];
#pragma unroll
    for (int i = 0; i < 8; i++) {
        float4 b = bs4[i];
        gv[4 * i] = b.x; gv[4 * i + 1] = b.y; gv[4 * i + 2] = b.z; gv[4 * i + 3] = b.w;
    }
    if (valid) {
#pragma unroll
        for (int i = 0; i < 8; i++) {
            float4 p = pv4[i];
            gv[4 * i] += p.x; gv[4 * i + 1] += p.y; gv[4 * i + 2] += p.z; gv[4 * i + 3] += p.w;
        }
    }

    float c8[8], h8[8];
#pragma unroll
    for (int u = 0; u < 8; u++) {
        int q = u & 3, tt = u >> 2;
        int ic = (tt << 4) + (q << 1);
        float cn = sigf_(gv[ic]) * tanhf_(gv[ic + 8]);
        c8[u] = cn;
        h8[u] = sigf_(gv[ic + 9]) * tanhf_(cn);
    }
    *(float4*)crow       = make_float4(c8[0], c8[1], c8[2], c8[3]);
    *(float4*)(crow + 4) = make_float4(c8[4], c8[5], c8[6], c8[7]);
    uint4 hw;
    hw.x = packh(__float2half(h8[0]), __float2half(h8[1]));
    hw.y = packh(__float2half(h8[2]), __float2half(h8[3]));
    hw.z = packh(__float2half(h8[4]), __float2half(h8[5]));
    hw.w = packh(__float2half(h8[6]), __float2half(h8[7]));
    *(uint4*)hrow = hw;
}

// ---------------------------------------------------------------------------
// gates_mma: steps 1..5, both dirs. fp16 1-term, single 32KB stage, 2 CTAs/SM,
// register-direct fused LSTM epilogue (permcol layout). [unchanged from R15]
// ---------------------------------------------------------------------------
__global__ void __launch_bounds__(256, 2) gates_mma(const int* __restrict__ x, int step)
{
    extern __shared__ unsigned char smraw[];
    uint32_t sb0 = smem_u32(smraw);
    uint32_t sb = (sb0 + 1023u) & ~1023u;
    unsigned char* smb = smraw + (sb - sb0);

    const int dir = blockIdx.z;
    const int nblk = blockIdx.x;
    const int m0 = blockIdx.y << 7;
    const int tid = threadIdx.x;
    const int lane = tid & 31, wid = tid >> 5;
    const int wm = wid >> 2, wn = wid & 3;
    const int buf = step & 1, nbuf = buf ^ 1;

    float* biasf = (float*)(smb + 32768);
    if (tid < 32)
        *(float4*)(biasf + (tid << 2)) = *(const float4*)(g_bsum[dir] + (nblk << 7) + (tid << 2));

    const uint4* srcA = (const uint4*)g_hA[dir][buf];

    float acc[4][4][4];
#pragma unroll
    for (int a = 0; a < 4; a++)
#pragma unroll
        for (int b = 0; b < 4; b++)
#pragma unroll
            for (int c = 0; c < 4; c++) acc[a][b][c] = 0.f;

    const int arow = (wm << 6) + (lane & 15);
    const int atop = (lane >> 4) << 4;
    const int brow = (wn << 5) + (lane & 7) + ((lane & 16) ? 8 : 0);
    const int btop = (lane & 8) ? 16 : 0;

    for (int kc = 0; kc < 4; kc++) {
#pragma unroll
        for (int i = 0; i < 4; i++) {
            int u = tid + (i << 8);
            int r = u >> 3, c16 = u & 7;
            uint32_t dst = sb + swz128((uint32_t)r * 128u + ((uint32_t)c16 << 4));
            cpasync16(dst, &srcA[(size_t)(m0 + r) * 32 + (kc << 3) + c16]);
        }
        {
            const unsigned char* src = &g_Bsw[dir][nblk][kc][0];
#pragma unroll
            for (int i = 0; i < 4; i++) {
                uint32_t o = ((uint32_t)tid + ((uint32_t)i << 8)) << 4;
                cpasync16(sb + 16384u + o, src + o);
            }
        }
        CPASYNC_COMMIT();
        CPASYNC_WAIT_0();
        __syncthreads();

        const uint32_t aB = sb, bB = sb + 16384u;
#pragma unroll
        for (int ks = 0; ks < 4; ks++) {
            const uint32_t kbyte = (uint32_t)ks << 5;
            uint32_t ah[4][4], bh[8];
#pragma unroll
            for (int mi = 0; mi < 4; mi++) {
                uint32_t off = swz128((uint32_t)(arow + mi * 16) * 128u + kbyte + (uint32_t)atop);
                ldsm4(ah[mi], aB + off);
            }
#pragma unroll
            for (int bi = 0; bi < 2; bi++) {
                uint32_t off = swz128((uint32_t)(brow + bi * 16) * 128u + kbyte + (uint32_t)btop);
                ldsm4(bh + bi * 4, bB + off);
            }
#pragma unroll
            for (int mi = 0; mi < 4; mi++)
#pragma unroll
                for (int ni = 0; ni < 4; ni++)
                    mma_f16(acc[mi][ni], ah[mi], bh + ni * 2);
        }
        if (kc < 3) __syncthreads();
    }

    // ---- register-direct fused epilogue ----
    const int q = lane & 3;
    const int rbl = (wm << 6) + (lane >> 2);
    const int ug0 = ((nblk << 2) + wn) << 3;
    const float* bs = biasf + (wn << 5);
    const bool finalstep = (step == WSw);

#pragma unroll
    for (int mi = 0; mi < 4; mi++) {
#pragma unroll
        for (int t2 = 0; t2 < 2; t2++) {
            const int row = m0 + rbl + mi * 16 + (t2 << 3);
            const int t = row & (Ss - 1), bidx = row >> 10;
            const int tp = dir ? (t + WSw - step) : (t - WSw + step);
            const bool valid = ((unsigned)tp < (unsigned)Ss);
            const int tok = valid ? x[(bidx << 10) + tp] : 0;
            const float* pvrow = g_PVp[dir] + (size_t)tok * G4H + (nblk << 7) + (wn << 5);
            float* crow = g_cst[dir] + (size_t)row * Hh + ug0;
            __half* hrow = g_hA[dir][nbuf] + (size_t)row * Hh + ug0;
            __half* frow = g_fcA + (size_t)row * FHh + dir * Hh + ug0;
#pragma unroll
            for (int tt = 0; tt < 2; tt++) {
                float gi = acc[mi][2 * tt][2 * t2];
                float gf = acc[mi][2 * tt][2 * t2 + 1];
                float gg = acc[mi][2 * tt + 1][2 * t2];
                float go = acc[mi][2 * tt + 1][2 * t2 + 1];
                const int ic = (tt << 4) + (q << 1);
                gi += bs[ic]; gf += bs[ic + 1]; gg += bs[ic + 8]; go += bs[ic + 9];
                if (valid) {
                    float2 pif = *(const float2*)(pvrow + ic);
                    float2 pgo = *(const float2*)(pvrow + ic + 8);
                    gi += pif.x; gf += pif.y; gg += pgo.x; go += pgo.y;
                }
                const int u = q + (tt << 2);
                float cv = crow[u];
                float cn = sigf_(gf) * cv + sigf_(gi) * tanhf_(gg);
                crow[u] = cn;
                float hv = sigf_(go) * tanhf_(cn);
                hrow[u] = __float2half(hv);
                if (finalstep) frow[u] = __float2half(leakyf_(hv));
            }
        }
    }
}

// ---------------------------------------------------------------------------
// fc1_mma + fused fc2 partial dot: never materializes fc1 activations.
// Each thread dots its leaky(acc+bias) fragment with fc2_w, quad-reduces,
// atomicAdds one partial per row per nblk into g_dot.
// ---------------------------------------------------------------------------
__global__ void __launch_bounds__(256, 2) fc1_mma(const float* __restrict__ fc1_b,
                                                  const float* __restrict__ fc2w)
{
    extern __shared__ unsigned char smraw[];
    uint32_t sb0 = smem_u32(smraw);
    uint32_t sb = (sb0 + 1023u) & ~1023u;
    unsigned char* smb = smraw + (sb - sb0);

    const int nblk = blockIdx.x;
    const int m0 = blockIdx.y << 7;
    const int tid = threadIdx.x;
    const int lane = tid & 31, wid = tid >> 5;
    const int wm = wid >> 2, wn = wid & 3;

    float* biasf = (float*)(smb + 32768);
    if (tid < 32)
        *(float4*)(biasf + (tid << 2)) = *(const float4*)(fc1_b + (nblk << 7) + (tid << 2));
    float* w2 = biasf + 128;
    if (tid >= 32 && tid < 64)
        *(float4*)(w2 + ((tid - 32) << 2)) = *(const float4*)(fc2w + (nblk << 7) + ((tid - 32) << 2));

    float acc[4][4][4];
#pragma unroll
    for (int a = 0; a < 4; a++)
#pragma unroll
        for (int b = 0; b < 4; b++)
#pragma unroll
            for (int c = 0; c < 4; c++) acc[a][b][c] = 0.f;

    const int arow = (wm << 6) + (lane & 15);
    const int atop = (lane >> 4) << 4;
    const int brow = (wn << 5) + (lane & 7) + ((lane & 16) ? 8 : 0);
    const int btop = (lane & 8) ? 16 : 0;

    for (int kc = 0; kc < 8; kc++) {
        const uint4* srcA = (const uint4*)g_fcA;
#pragma unroll
        for (int i = 0; i < 4; i++) {
            int u = tid + (i << 8);
            int r = u >> 3, c16 = u & 7;
            uint32_t dst = sb + swz128((uint32_t)r * 128u + ((uint32_t)c16 << 4));
            cpasync16(dst, &srcA[(size_t)(m0 + r) * 64 + (kc << 3) + c16]);
        }
        {
            const unsigned char* src = &g_fc1Bsw[nblk][kc][0];
#pragma unroll
            for (int i = 0; i < 4; i++) {
                uint32_t o = ((uint32_t)tid + ((uint32_t)i << 8)) << 4;
                cpasync16(sb + 16384u + o, src + o);
            }
        }
        CPASYNC_COMMIT();
        CPASYNC_WAIT_0();
        __syncthreads();

        const uint32_t aB = sb, bB = sb + 16384u;
#pragma unroll
        for (int ks = 0; ks < 4; ks++) {
            const uint32_t kbyte = (uint32_t)ks << 5;
            uint32_t ah[4][4], bh[8];
#pragma unroll
            for (int mi = 0; mi < 4; mi++) {
                uint32_t off = swz128((uint32_t)(arow + mi * 16) * 128u + kbyte + (uint32_t)atop);
                ldsm4(ah[mi], aB + off);
            }
#pragma unroll
            for (int bi = 0; bi < 2; bi++) {
                uint32_t off = swz128((uint32_t)(brow + bi * 16) * 128u + kbyte + (uint32_t)btop);
                ldsm4(bh + bi * 4, bB + off);
            }
#pragma unroll
            for (int mi = 0; mi < 4; mi++)
#pragma unroll
                for (int ni = 0; ni < 4; ni++)
                    mma_f16(acc[mi][ni], ah[mi], bh + ni * 2);
        }
        if (kc < 7) __syncthreads();
    }

    // fused epilogue: leaky + fc2 partial dot; quad-reduce; atomicAdd per row
#pragma unroll
    for (int mi = 0; mi < 4; mi++) {
        int r0 = m0 + (wm << 6) + mi * 16 + (lane >> 2);
        float dA = 0.f, dB = 0.f;
#pragma unroll
        for (int ni = 0; ni < 4; ni++) {
            int cl = (wn << 5) + ni * 8 + ((lane & 3) << 1);
            float b0 = biasf[cl], b1 = biasf[cl + 1];
            float w0 = w2[cl], w1 = w2[cl + 1];
            dA += leakyf_(acc[mi][ni][0] + b0) * w0 + leakyf_(acc[mi][ni][1] + b1) * w1;
            dB += leakyf_(acc[mi][ni][2] + b0) * w0 + leakyf_(acc[mi][ni][3] + b1) * w1;
        }
        dA += __shfl_xor_sync(0xffffffffu, dA, 1);
        dA += __shfl_xor_sync(0xffffffffu, dA, 2);
        dB += __shfl_xor_sync(0xffffffffu, dB, 1);
        dB += __shfl_xor_sync(0xffffffffu, dB, 2);
        if ((lane & 3) == 0) {
            atomicAdd(g_dot + r0, dA);
            atomicAdd(g_dot + r0 + 8, dB);
        }
    }
}

// ---------------------------------------------------------------------------
// zero_dot / out_sig
// ---------------------------------------------------------------------------
__global__ void __launch_bounds__(256) zero_dot()
{
    int i = blockIdx.x * 256 + threadIdx.x;
    if (i < NTOK) g_dot[i] = 0.f;
}
__global__ void __launch_bounds__(256) out_sig(const float* __restrict__ b,
                                               float* __restrict__ out)
{
    int i = blockIdx.x * 256 + threadIdx.x;
    if (i < NTOK) out[i] = sigf_(g_dot[i] + b[0]);
}

// ---------------------------------------------------------------------------
extern "C" void kernel_launch(void* const* d_in, const int* in_sizes, int n_in,
                              void* d_out, int out_size)
{
    const int*   x      = (const int*)  d_in[0];
    const float* embed  = (const float*)d_in[1];
    const float* Wih_f  = (const float*)d_in[2];
    const float* Whh_f  = (const float*)d_in[3];
    const float* bih_f  = (const float*)d_in[4];
    const float* bhh_f  = (const float*)d_in[5];
    const float* Wih_b  = (const float*)d_in[6];
    const float* Whh_b  = (const float*)d_in[7];
    const float* bih_b  = (const float*)d_in[8];
    const float* bhh_b  = (const float*)d_in[9];
    const float* fc1_w  = (const float*)d_in[10];
    const float* fc1_b  = (const float*)d_in[11];
    const float* fc2_w  = (const float*)d_in[12];
    const float* fc2_b  = (const float*)d_in[13];
    float* out = (float*)d_out;

    cudaFuncSetAttribute(gates_mma, cudaFuncAttributeMaxDynamicSharedMemorySize, SB_SMEM);
    cudaFuncSetAttribute(fc1_mma,   cudaFuncAttributeMaxDynamicSharedMemorySize, SB_SMEM);
    cudaFuncSetAttribute(pv_mma,    cudaFuncAttributeMaxDynamicSharedMemorySize, PV_SMEM);

    prep_all<<<640, 256>>>(Whh_f, Whh_b, Wih_f, Wih_b, fc1_w,
                           bih_f, bhh_f, bih_b, bhh_b);
    pv_mma<<<dim3(8, 63, 2), 256, PV_SMEM>>>(embed);

    // step 0 (h0 = 0): exact elementwise init, no GEMM
    gates_init<<<4096, 256>>>(x);
    zero_dot<<<64, 256>>>();

    for (int k = 1; k <= WSw; k++) {
        gates_mma<<<dim3(8, NTOK / 128, 2), 256, SB_SMEM>>>(x, k);
    }

    fc1_mma<<<dim3(4, 128), 256, SB_SMEM>>>(fc1_b, fc2_w);
    out_sig<<<64, 256>>>(fc2_b, out);
}

// round 17
// speedup vs baseline: 1.7655x; 1.3190x over previous
#include <cuda_runtime.h>
#include <cuda_fp16.h>
#include <math.h>
#include <stdint.h>

#define Bb   16
#define Ss   1024
#define Ee   256
#define Hh   256
#define FHh  512
#define Vv   8000
#define WSw  5
#define NTOK (Bb*Ss)     /* 16384 */
#define G4H  (4*Hh)      /* 1024  */

// ---------------- scratch (device globals; no dynamic allocation) ----------
__device__ __half g_PVp[2][(size_t)Vv * G4H];           // permuted input projections (fp16)
__device__ __half g_hA[2][2][(size_t)NTOK * Hh];        // [dir][pingpong] h as fp16
__device__ float g_cst[2][(size_t)NTOK * Hh];           // [dir] c state
__device__ __half g_fcA[(size_t)NTOK * FHh];            // leaky(h) concat, fc1 A (fp16)
__device__ float g_dot[NTOK];                           // fc2 partial dots
// fp16 weights, col-permuted, pre-swizzled tiles (128 rows x 64 k = 16KB)
__device__ unsigned char g_Bsw[2][8][4][16384];         // Whh  [dir][nblk][kc]
__device__ unsigned char g_BswIH[2][8][4][16384];       // Wih  [dir][nblk][kc]
__device__ unsigned char g_fc1Bsw[4][8][16384];         // fc1_w [nblk][kc]
__device__ float g_bsum[2][G4H];                        // permuted bih+bhh

// fast activations
__device__ __forceinline__ float sigf_(float x) {
    return __fdividef(1.0f, 1.0f + __expf(-x));
}
__device__ __forceinline__ float tanhf_(float x) {
    x = fminf(fmaxf(x, -15.0f), 15.0f);
    float e = __expf(2.0f * x);
    return __fdividef(e - 1.0f, e + 1.0f);
}
__device__ __forceinline__ float leakyf_(float x)   { return x > 0.0f ? x : 0.01f * x; }
__device__ __forceinline__ uint32_t swz128(uint32_t off) { return off ^ ((off >> 3) & 0x70); }
__device__ __forceinline__ uint32_t smem_u32(const void* p) {
    uint32_t a;
    asm("{ .reg .u64 t; cvta.to.shared.u64 t, %1; cvt.u32.u64 %0, t; }" : "=r"(a) : "l"(p));
    return a;
}
__device__ __forceinline__ void ldsm4(uint32_t* r, uint32_t addr) {
    asm volatile("ldmatrix.sync.aligned.m8n8.x4.shared.b16 {%0,%1,%2,%3}, [%4];"
        : "=r"(r[0]), "=r"(r[1]), "=r"(r[2]), "=r"(r[3]) : "r"(addr));
}
__device__ __forceinline__ void mma_f16(float* d, const uint32_t* a, const uint32_t* b) {
    asm volatile("mma.sync.aligned.m16n8k16.row.col.f32.f16.f16.f32 "
        "{%0,%1,%2,%3}, {%4,%5,%6,%7}, {%8,%9}, {%0,%1,%2,%3};"
        : "+f"(d[0]), "+f"(d[1]), "+f"(d[2]), "+f"(d[3])
        : "r"(a[0]), "r"(a[1]), "r"(a[2]), "r"(a[3]), "r"(b[0]), "r"(b[1]));
}
__device__ __forceinline__ void cpasync16(uint32_t dst, const void* src) {
    asm volatile("cp.async.cg.shared.global [%0], [%1], 16;" :: "r"(dst), "l"(src));
}
#define CPASYNC_COMMIT() asm volatile("cp.async.commit_group;" ::: "memory")
#define CPASYNC_WAIT_0() asm volatile("cp.async.wait_group 0;" ::: "memory")

__device__ __forceinline__ uint32_t packh(__half a, __half b) {
    unsigned short ua = *(unsigned short*)&a, ub = *(unsigned short*)&b;
    return (uint32_t)ua | ((uint32_t)ub << 16);
}
__device__ __forceinline__ float2 h2f2(uint32_t bits) {
    __half2 h = *(__half2*)&bits;
    return __half22float2(h);
}

// permutation: unit u (0..255), gate g (0..3) -> permuted col
// p = (u>>3)*32 + ((u>>2)&1)*16 + (g>>1)*8 + (u&3)*2 + (g&1)
__device__ __host__ __forceinline__ int permcol(int u, int g) {
    return ((u >> 3) << 5) | (((u >> 2) & 1) << 4) | ((g >> 1) << 3) | ((u & 3) << 1) | (g & 1);
}

#define PV_SMEM  (1024 + 32768 + 512)
#define SB_SMEM  (1024 + 32768 + 512)

// ---------------------------------------------------------------------------
// prep_all
// ---------------------------------------------------------------------------
__global__ void __launch_bounds__(256) prep_all(const float* __restrict__ Whf, const float* __restrict__ Whb,
                                                const float* __restrict__ Wif, const float* __restrict__ Wib,
                                                const float* __restrict__ fc1w,
                                                const float* __restrict__ bihf, const float* __restrict__ bhhf,
                                                const float* __restrict__ bihb, const float* __restrict__ bhhb)
{
    const int blk = blockIdx.x;
    const int tid = threadIdx.x;
    if (blk < 512) {
        const int sect = blk >> 8;                       // 0 = Whh, 1 = Wih
        int idx = (blk & 255) * 256 + tid;
        int dir = idx >> 15;
        int r = idx & 32767;
        int n = r >> 5;
        int k8 = (r & 31) << 3;
        const float* W = sect ? (dir ? Wib : Wif) : (dir ? Whb : Whf);
        int unit = n & 255, gate = n >> 8;
        int p = permcol(unit, gate);
        int nblk = p >> 7, prow = p & 127;
        float4 v0 = *(const float4*)(W + (size_t)n * Hh + k8);
        float4 v1 = *(const float4*)(W + (size_t)n * Hh + k8 + 4);
        float vals[8] = {v0.x, v0.y, v0.z, v0.w, v1.x, v1.y, v1.z, v1.w};
#pragma unroll
        for (int j = 0; j < 8; j++) {
            int k = k8 + j;
            int kc = k >> 6, kb = k & 63;
            uint32_t off = swz128((uint32_t)prow * 128u + (uint32_t)kb * 2u);
            __half hv = __float2half(vals[j]);
            if (sect == 0) *(__half*)(&g_Bsw[dir][nblk][kc][off]) = hv;
            else           *(__half*)(&g_BswIH[dir][nblk][kc][off]) = hv;
        }
        if (sect == 0 && k8 == 0) {
            const float* bi = dir ? bihb : bihf;
            const float* bh = dir ? bhhb : bhhf;
            g_bsum[dir][p] = bi[n] + bh[n];
        }
    } else {
        int idx = (blk - 512) * 256 + tid;
        int n = idx >> 6;
        int k8 = (idx & 63) << 3;
        int nblk = n >> 7, prow = n & 127;
        float4 v0 = *(const float4*)(fc1w + (size_t)n * FHh + k8);
        float4 v1 = *(const float4*)(fc1w + (size_t)n * FHh + k8 + 4);
        float vals[8] = {v0.x, v0.y, v0.z, v0.w, v1.x, v1.y, v1.z, v1.w};
#pragma unroll
        for (int j = 0; j < 8; j++) {
            int k = k8 + j;
            int kc = k >> 6, kb = k & 63;
            uint32_t off = swz128((uint32_t)prow * 128u + (uint32_t)kb * 2u);
            *(__half*)(&g_fc1Bsw[nblk][kc][off]) = __float2half(vals[j]);
        }
    }
}

// ---------------------------------------------------------------------------
// pv_mma: PVp[dir] = embed(row0=0) @ Wih^T, fp16 1-term, fp16 output.
// ---------------------------------------------------------------------------
__global__ void __launch_bounds__(256) pv_mma(const float* __restrict__ embed)
{
    extern __shared__ unsigned char smraw[];
    uint32_t sb0 = smem_u32(smraw);
    uint32_t sb = (sb0 + 1023u) & ~1023u;
    unsigned char* smb = smraw + (sb - sb0);

    const int dir = blockIdx.z;
    const int nblk = blockIdx.x;
    const int m0 = blockIdx.y << 7;
    const int tid = threadIdx.x;
    const int lane = tid & 31, wid = tid >> 5;
    const int wm = wid >> 2, wn = wid & 3;

    float acc[4][4][4];
#pragma unroll
    for (int a = 0; a < 4; a++)
#pragma unroll
        for (int b = 0; b < 4; b++)
#pragma unroll
            for (int c = 0; c < 4; c++) acc[a][b][c] = 0.f;

    const uint32_t aBase = sb, bBase = sb + 16384u;
    const int arow = (wm << 6) + (lane & 15);
    const int atop = (lane >> 4) << 4;
    const int brow = (wn << 5) + (lane & 7) + ((lane & 16) ? 8 : 0);
    const int btop = (lane & 8) ? 16 : 0;

    for (int kc = 0; kc < 4; kc++) {
#pragma unroll
        for (int i = 0; i < 4; i++) {
            int u = tid + (i << 8);
            int r = u >> 3, c8 = u & 7;
            int g = m0 + r;
            float vals[8];
            if (g == 0 || g >= Vv) {
#pragma unroll
                for (int j = 0; j < 8; j++) vals[j] = 0.f;
            } else {
                float4 v0 = *(const float4*)(embed + (size_t)g * Ee + (kc << 6) + (c8 << 3));
                float4 v1 = *(const float4*)(embed + (size_t)g * Ee + (kc << 6) + (c8 << 3) + 4);
                vals[0] = v0.x; vals[1] = v0.y; vals[2] = v0.z; vals[3] = v0.w;
                vals[4] = v1.x; vals[5] = v1.y; vals[6] = v1.z; vals[7] = v1.w;
            }
            uint4 hv;
            hv.x = packh(__float2half(vals[0]), __float2half(vals[1]));
            hv.y = packh(__float2half(vals[2]), __float2half(vals[3]));
            hv.z = packh(__float2half(vals[4]), __float2half(vals[5]));
            hv.w = packh(__float2half(vals[6]), __float2half(vals[7]));
            *(uint4*)(smb + swz128((uint32_t)r * 128u + ((uint32_t)c8 << 4))) = hv;
        }
        {
            const uint4* src = (const uint4*)&g_BswIH[dir][nblk][kc][0];
            uint4* dst = (uint4*)(smb + 16384);
#pragma unroll
            for (int i = 0; i < 4; i++) dst[tid + (i << 8)] = src[tid + (i << 8)];
        }
        __syncthreads();

#pragma unroll
        for (int ks = 0; ks < 4; ks++) {
            const uint32_t kbyte = (uint32_t)ks << 5;
            uint32_t ah[4][4], bh[8];
#pragma unroll
            for (int mi = 0; mi < 4; mi++) {
                uint32_t off = swz128((uint32_t)(arow + mi * 16) * 128u + kbyte + (uint32_t)atop);
                ldsm4(ah[mi], aBase + off);
            }
#pragma unroll
            for (int bi = 0; bi < 2; bi++) {
                uint32_t off = swz128((uint32_t)(brow + bi * 16) * 128u + kbyte + (uint32_t)btop);
                ldsm4(bh + bi * 4, bBase + off);
            }
#pragma unroll
            for (int mi = 0; mi < 4; mi++)
#pragma unroll
                for (int ni = 0; ni < 4; ni++)
                    mma_f16(acc[mi][ni], ah[mi], bh + ni * 2);
        }
        __syncthreads();
    }

    __half* out = g_PVp[dir];
#pragma unroll
    for (int mi = 0; mi < 4; mi++) {
        int r0 = m0 + (wm << 6) + mi * 16 + (lane >> 2);
#pragma unroll
        for (int ni = 0; ni < 4; ni++) {
            int c0 = (nblk << 7) + (wn << 5) + ni * 8 + ((lane & 3) << 1);
            if (r0 < Vv) {
                __half2 h = __floats2half2_rn(acc[mi][ni][0], acc[mi][ni][1]);
                *(__half2*)(out + (size_t)r0 * G4H + c0) = h;
            }
            if (r0 + 8 < Vv) {
                __half2 h = __floats2half2_rn(acc[mi][ni][2], acc[mi][ni][3]);
                *(__half2*)(out + (size_t)(r0 + 8) * G4H + c0) = h;
            }
        }
    }
}

// ---------------------------------------------------------------------------
// gates_init: step 0 exactly (h0 = c0 = 0). Vectorized fp16 PV loads.
// ---------------------------------------------------------------------------
__global__ void __launch_bounds__(256) gates_init(const int* __restrict__ x)
{
    int idx = blockIdx.x * 256 + threadIdx.x;          // 1,048,576 threads
    int dir = idx >> 19;
    int r = idx & 524287;
    int row = r >> 5;
    int g32 = r & 31;                                  // 8-unit group (0..31)
    int t = row & (Ss - 1), bidx = row >> 10;
    int tp = dir ? (t + WSw) : (t - WSw);
    bool valid = ((unsigned)tp < (unsigned)Ss);
    int tok = valid ? x[(bidx << 10) + tp] : 0;
    const uint4* pv4 = (const uint4*)(g_PVp[dir] + (size_t)tok * G4H + (g32 << 5));
    const float4* bs4 = (const float4*)(g_bsum[dir] + (g32 << 5));
    float* crow = g_cst[dir] + (size_t)row * Hh + (g32 << 3);
    __half* hrow = g_hA[dir][1] + (size_t)row * Hh + (g32 << 3);

    float gv[32];
#pragma unroll
    for (int i = 0; i < 8; i++) {
        float4 b = bs4[i];
        gv[4 * i] = b.x; gv[4 * i + 1] = b.y; gv[4 * i + 2] = b.z; gv[4 * i + 3] = b.w;
    }
    if (valid) {
#pragma unroll
        for (int i = 0; i < 4; i++) {
            uint4 p = pv4[i];                          // 8 halves
            float2 f0 = h2f2(p.x), f1 = h2f2(p.y), f2 = h2f2(p.z), f3 = h2f2(p.w);
            gv[8 * i]     += f0.x; gv[8 * i + 1] += f0.y;
            gv[8 * i + 2] += f1.x; gv[8 * i + 3] += f1.y;
            gv[8 * i + 4] += f2.x; gv[8 * i + 5] += f2.y;
            gv[8 * i + 6] += f3.x; gv[8 * i + 7] += f3.y;
        }
    }

    float c8[8], h8[8];
#pragma unroll
    for (int u = 0; u < 8; u++) {
        int q = u & 3, tt = u >> 2;
        int ic = (tt << 4) + (q << 1);
        float cn = sigf_(gv[ic]) * tanhf_(gv[ic + 8]);
        c8[u] = cn;
        h8[u] = sigf_(gv[ic + 9]) * tanhf_(cn);
    }
    *(float4*)crow       = make_float4(c8[0], c8[1], c8[2], c8[3]);
    *(float4*)(crow + 4) = make_float4(c8[4], c8[5], c8[6], c8[7]);
    uint4 hw;
    hw.x = packh(__float2half(h8[0]), __float2half(h8[1]));
    hw.y = packh(__float2half(h8[2]), __float2half(h8[3]));
    hw.z = packh(__float2half(h8[4]), __float2half(h8[5]));
    hw.w = packh(__float2half(h8[6]), __float2half(h8[7]));
    *(uint4*)hrow = hw;
}

// ---------------------------------------------------------------------------
// gates_mma: steps 1..5, both dirs. fp16 1-term, single 32KB stage, 2 CTAs/SM,
// register-direct fused LSTM epilogue with fp16 PV gather.
// ---------------------------------------------------------------------------
__global__ void __launch_bounds__(256, 2) gates_mma(const int* __restrict__ x, int step)
{
    extern __shared__ unsigned char smraw[];
    uint32_t sb0 = smem_u32(smraw);
    uint32_t sb = (sb0 + 1023u) & ~1023u;
    unsigned char* smb = smraw + (sb - sb0);

    const int dir = blockIdx.z;
    const int nblk = blockIdx.x;
    const int m0 = blockIdx.y << 7;
    const int tid = threadIdx.x;
    const int lane = tid & 31, wid = tid >> 5;
    const int wm = wid >> 2, wn = wid & 3;
    const int buf = step & 1, nbuf = buf ^ 1;

    float* biasf = (float*)(smb + 32768);
    if (tid < 32)
        *(float4*)(biasf + (tid << 2)) = *(const float4*)(g_bsum[dir] + (nblk << 7) + (tid << 2));

    const uint4* srcA = (const uint4*)g_hA[dir][buf];

    float acc[4][4][4];
#pragma unroll
    for (int a = 0; a < 4; a++)
#pragma unroll
        for (int b = 0; b < 4; b++)
#pragma unroll
            for (int c = 0; c < 4; c++) acc[a][b][c] = 0.f;

    const int arow = (wm << 6) + (lane & 15);
    const int atop = (lane >> 4) << 4;
    const int brow = (wn << 5) + (lane & 7) + ((lane & 16) ? 8 : 0);
    const int btop = (lane & 8) ? 16 : 0;

    for (int kc = 0; kc < 4; kc++) {
#pragma unroll
        for (int i = 0; i < 4; i++) {
            int u = tid + (i << 8);
            int r = u >> 3, c16 = u & 7;
            uint32_t dst = sb + swz128((uint32_t)r * 128u + ((uint32_t)c16 << 4));
            cpasync16(dst, &srcA[(size_t)(m0 + r) * 32 + (kc << 3) + c16]);
        }
        {
            const unsigned char* src = &g_Bsw[dir][nblk][kc][0];
#pragma unroll
            for (int i = 0; i < 4; i++) {
                uint32_t o = ((uint32_t)tid + ((uint32_t)i << 8)) << 4;
                cpasync16(sb + 16384u + o, src + o);
            }
        }
        CPASYNC_COMMIT();
        CPASYNC_WAIT_0();
        __syncthreads();

        const uint32_t aB = sb, bB = sb + 16384u;
#pragma unroll
        for (int ks = 0; ks < 4; ks++) {
            const uint32_t kbyte = (uint32_t)ks << 5;
            uint32_t ah[4][4], bh[8];
#pragma unroll
            for (int mi = 0; mi < 4; mi++) {
                uint32_t off = swz128((uint32_t)(arow + mi * 16) * 128u + kbyte + (uint32_t)atop);
                ldsm4(ah[mi], aB + off);
            }
#pragma unroll
            for (int bi = 0; bi < 2; bi++) {
                uint32_t off = swz128((uint32_t)(brow + bi * 16) * 128u + kbyte + (uint32_t)btop);
                ldsm4(bh + bi * 4, bB + off);
            }
#pragma unroll
            for (int mi = 0; mi < 4; mi++)
#pragma unroll
                for (int ni = 0; ni < 4; ni++)
                    mma_f16(acc[mi][ni], ah[mi], bh + ni * 2);
        }
        if (kc < 3) __syncthreads();
    }

    // ---- register-direct fused epilogue (fp16 PV) ----
    const int q = lane & 3;
    const int rbl = (wm << 6) + (lane >> 2);
    const int ug0 = ((nblk << 2) + wn) << 3;
    const float* bs = biasf + (wn << 5);
    const bool finalstep = (step == WSw);

#pragma unroll
    for (int mi = 0; mi < 4; mi++) {
#pragma unroll
        for (int t2 = 0; t2 < 2; t2++) {
            const int row = m0 + rbl + mi * 16 + (t2 << 3);
            const int t = row & (Ss - 1), bidx = row >> 10;
            const int tp = dir ? (t + WSw - step) : (t - WSw + step);
            const bool valid = ((unsigned)tp < (unsigned)Ss);
            const int tok = valid ? x[(bidx << 10) + tp] : 0;
            const __half* pvrow = g_PVp[dir] + (size_t)tok * G4H + (nblk << 7) + (wn << 5);
            float* crow = g_cst[dir] + (size_t)row * Hh + ug0;
            __half* hrow = g_hA[dir][nbuf] + (size_t)row * Hh + ug0;
            __half* frow = g_fcA + (size_t)row * FHh + dir * Hh + ug0;
#pragma unroll
            for (int tt = 0; tt < 2; tt++) {
                float gi = acc[mi][2 * tt][2 * t2];
                float gf = acc[mi][2 * tt][2 * t2 + 1];
                float gg = acc[mi][2 * tt + 1][2 * t2];
                float go = acc[mi][2 * tt + 1][2 * t2 + 1];
                const int ic = (tt << 4) + (q << 1);
                gi += bs[ic]; gf += bs[ic + 1]; gg += bs[ic + 8]; go += bs[ic + 9];
                if (valid) {
                    float2 pif = __half22float2(*(const __half2*)(pvrow + ic));
                    float2 pgo = __half22float2(*(const __half2*)(pvrow + ic + 8));
                    gi += pif.x; gf += pif.y; gg += pgo.x; go += pgo.y;
                }
                const int u = q + (tt << 2);
                float cv = crow[u];
                float cn = sigf_(gf) * cv + sigf_(gi) * tanhf_(gg);
                crow[u] = cn;
                float hv = sigf_(go) * tanhf_(cn);
                hrow[u] = __float2half(hv);
                if (finalstep) frow[u] = __float2half(leakyf_(hv));
            }
        }
    }
}

// ---------------------------------------------------------------------------
// fc1_mma + fused fc2 partial dot
// ---------------------------------------------------------------------------
__global__ void __launch_bounds__(256, 2) fc1_mma(const float* __restrict__ fc1_b,
                                                  const float* __restrict__ fc2w)
{
    extern __shared__ unsigned char smraw[];
    uint32_t sb0 = smem_u32(smraw);
    uint32_t sb = (sb0 + 1023u) & ~1023u;
    unsigned char* smb = smraw + (sb - sb0);

    const int nblk = blockIdx.x;
    const int m0 = blockIdx.y << 7;
    const int tid = threadIdx.x;
    const int lane = tid & 31, wid = tid >> 5;
    const int wm = wid >> 2, wn = wid & 3;

    float* biasf = (float*)(smb + 32768);
    if (tid < 32)
        *(float4*)(biasf + (tid << 2)) = *(const float4*)(fc1_b + (nblk << 7) + (tid << 2));
    float* w2 = biasf + 128;
    if (tid >= 32 && tid < 64)
        *(float4*)(w2 + ((tid - 32) << 2)) = *(const float4*)(fc2w + (nblk << 7) + ((tid - 32) << 2));

    float acc[4][4][4];
#pragma unroll
    for (int a = 0; a < 4; a++)
#pragma unroll
        for (int b = 0; b < 4; b++)
#pragma unroll
            for (int c = 0; c < 4; c++) acc[a][b][c] = 0.f;

    const int arow = (wm << 6) + (lane & 15);
    const int atop = (lane >> 4) << 4;
    const int brow = (wn << 5) + (lane & 7) + ((lane & 16) ? 8 : 0);
    const int btop = (lane & 8) ? 16 : 0;

    for (int kc = 0; kc < 8; kc++) {
        const uint4* srcA = (const uint4*)g_fcA;
#pragma unroll
        for (int i = 0; i < 4; i++) {
            int u = tid + (i << 8);
            int r = u >> 3, c16 = u & 7;
            uint32_t dst = sb + swz128((uint32_t)r * 128u + ((uint32_t)c16 << 4));
            cpasync16(dst, &srcA[(size_t)(m0 + r) * 64 + (kc << 3) + c16]);
        }
        {
            const unsigned char* src = &g_fc1Bsw[nblk][kc][0];
#pragma unroll
            for (int i = 0; i < 4; i++) {
                uint32_t o = ((uint32_t)tid + ((uint32_t)i << 8)) << 4;
                cpasync16(sb + 16384u + o, src + o);
            }
        }
        CPASYNC_COMMIT();
        CPASYNC_WAIT_0();
        __syncthreads();

        const uint32_t aB = sb, bB = sb + 16384u;
#pragma unroll
        for (int ks = 0; ks < 4; ks++) {
            const uint32_t kbyte = (uint32_t)ks << 5;
            uint32_t ah[4][4], bh[8];
#pragma unroll
            for (int mi = 0; mi < 4; mi++) {
                uint32_t off = swz128((uint32_t)(arow + mi * 16) * 128u + kbyte + (uint32_t)atop);
                ldsm4(ah[mi], aB + off);
            }
#pragma unroll
            for (int bi = 0; bi < 2; bi++) {
                uint32_t off = swz128((uint32_t)(brow + bi * 16) * 128u + kbyte + (uint32_t)btop);
                ldsm4(bh + bi * 4, bB + off);
            }
#pragma unroll
            for (int mi = 0; mi < 4; mi++)
#pragma unroll
                for (int ni = 0; ni < 4; ni++)
                    mma_f16(acc[mi][ni], ah[mi], bh + ni * 2);
        }
        if (kc < 7) __syncthreads();
    }

    // fused epilogue: leaky + fc2 partial dot; quad-reduce; atomicAdd per row
#pragma unroll
    for (int mi = 0; mi < 4; mi++) {
        int r0 = m0 + (wm << 6) + mi * 16 + (lane >> 2);
        float dA = 0.f, dB = 0.f;
#pragma unroll
        for (int ni = 0; ni < 4; ni++) {
            int cl = (wn << 5) + ni * 8 + ((lane & 3) << 1);
            float b0 = biasf[cl], b1 = biasf[cl + 1];
            float w0 = w2[cl], w1 = w2[cl + 1];
            dA += leakyf_(acc[mi][ni][0] + b0) * w0 + leakyf_(acc[mi][ni][1] + b1) * w1;
            dB += leakyf_(acc[mi][ni][2] + b0) * w0 + leakyf_(acc[mi][ni][3] + b1) * w1;
        }
        dA += __shfl_xor_sync(0xffffffffu, dA, 1);
        dA += __shfl_xor_sync(0xffffffffu, dA, 2);
        dB += __shfl_xor_sync(0xffffffffu, dB, 1);
        dB += __shfl_xor_sync(0xffffffffu, dB, 2);
        if ((lane & 3) == 0) {
            atomicAdd(g_dot + r0, dA);
            atomicAdd(g_dot + r0 + 8, dB);
        }
    }
}

// ---------------------------------------------------------------------------
// zero_dot / out_sig
// ---------------------------------------------------------------------------
__global__ void __launch_bounds__(256) zero_dot()
{
    int i = blockIdx.x * 256 + threadIdx.x;
    if (i < NTOK) g_dot[i] = 0.f;
}
__global__ void __launch_bounds__(256) out_sig(const float* __restrict__ b,
                                               float* __restrict__ out)
{
    int i = blockIdx.x * 256 + threadIdx.x;
    if (i < NTOK) out[i] = sigf_(g_dot[i] + b[0]);
}

// ---------------------------------------------------------------------------
extern "C" void kernel_launch(void* const* d_in, const int* in_sizes, int n_in,
                              void* d_out, int out_size)
{
    const int*   x      = (const int*)  d_in[0];
    const float* embed  = (const float*)d_in[1];
    const float* Wih_f  = (const float*)d_in[2];
    const float* Whh_f  = (const float*)d_in[3];
    const float* bih_f  = (const float*)d_in[4];
    const float* bhh_f  = (const float*)d_in[5];
    const float* Wih_b  = (const float*)d_in[6];
    const float* Whh_b  = (const float*)d_in[7];
    const float* bih_b  = (const float*)d_in[8];
    const float* bhh_b  = (const float*)d_in[9];
    const float* fc1_w  = (const float*)d_in[10];
    const float* fc1_b  = (const float*)d_in[11];
    const float* fc2_w  = (const float*)d_in[12];
    const float* fc2_b  = (const float*)d_in[13];
    float* out = (float*)d_out;

    cudaFuncSetAttribute(gates_mma, cudaFuncAttributeMaxDynamicSharedMemorySize, SB_SMEM);
    cudaFuncSetAttribute(fc1_mma,   cudaFuncAttributeMaxDynamicSharedMemorySize, SB_SMEM);
    cudaFuncSetAttribute(pv_mma,    cudaFuncAttributeMaxDynamicSharedMemorySize, PV_SMEM);

    prep_all<<<640, 256>>>(Whh_f, Whh_b, Wih_f, Wih_b, fc1_w,
                           bih_f, bhh_f, bih_b, bhh_b);
    pv_mma<<<dim3(8, 63, 2), 256, PV_SMEM>>>(embed);

    // step 0 (h0 = 0): exact elementwise init, no GEMM
    gates_init<<<4096, 256>>>(x);
    zero_dot<<<64, 256>>>();

    for (int k = 1; k <= WSw; k++) {
        gates_mma<<<dim3(8, NTOK / 128, 2), 256, SB_SMEM>>>(x, k);
    }

    fc1_mma<<<dim3(4, 128), 256, SB_SMEM>>>(fc1_b, fc2_w);
    out_sig<<<64, 256>>>(fc2_b, out);
}